// round 10
// baseline (speedup 1.0000x reference)
#include <cuda_runtime.h>
#include <cstdint>

#define Cn 16
#define Hn 512
#define Wn 512
#define HWn (Hn*Wn)
#define NSTEPS 8
#define GRIDX 152
#define NTHREADS 256
#define NT2 4096          // 64-px tiles
#define TSTRIDE 304       // 152 blocks x 2 groups
#define RS2 68            // rows segment stride (66 used + pad); 68%32==4 like 132
#define HS  132

// ---- smem float offsets ----
#define OFF_W1H 0                        // 10240 (float2[10kc][128n][4q])
#define OFF_W1L 10240                    // 10240
#define OFF_W2H 20480                    // 2048  (float2[16kc][16n][4q])
#define OFF_W2L 22528                    // 2048
#define OFF_B1  24576                    // 128
#define OFF_B2  24704                    // 16
#define OFF_R   24720                    // 4 buffers (2 groups x 2) x 48*RS2
#define RBUFSZ  (48*RS2)                 // 3264
#define OFF_H   (OFF_R + 4*RBUFSZ)       // 37776 ; 2 groups x 64*HS
#define HBUFSZ  (64*HS)                  // 8448
#define SMEM_FLOATS (OFF_H + 2*HBUFSZ)   // 54672 -> 218688 B

__device__ float g_bufA[Cn*HWn];
__device__ float g_bufB[Cn*HWn];
__device__ float g_w1ph[10240];
__device__ float g_w1pl[10240];
__device__ float g_w2ph[2048];
__device__ float g_w2pl[2048];

__device__ __forceinline__ uint32_t tf32h(float x) {
    uint32_t u;
    asm("cvt.rna.tf32.f32 %0, %1;" : "=r"(u) : "f"(x));
    return u;
}
__device__ __forceinline__ uint32_t smem_u32(const void* p) {
    uint32_t a;
    asm("{ .reg .u64 t; cvta.to.shared.u64 t, %1; cvt.u32.u64 %0, t; }" : "=r"(a) : "l"(p));
    return a;
}
__device__ __forceinline__ void cpa4(uint32_t d, const float* g) {
    asm volatile("cp.async.ca.shared.global [%0], [%1], 4;" :: "r"(d), "l"(g));
}
#define CP_COMMIT() asm volatile("cp.async.commit_group;" ::: "memory")
#define CP_WAIT0()  asm volatile("cp.async.wait_group 0;" ::: "memory")
#define BARG(id)    asm volatile("bar.sync %0, 128;" :: "r"(id) : "memory")

__device__ __forceinline__ void mma8(float* d,
    uint32_t a0, uint32_t a1, uint32_t a2, uint32_t a3,
    uint32_t b0, uint32_t b1)
{
    asm volatile(
        "mma.sync.aligned.m16n8k8.row.col.f32.tf32.tf32.f32 "
        "{%0,%1,%2,%3}, {%4,%5,%6,%7}, {%8,%9}, {%0,%1,%2,%3};"
        : "+f"(d[0]), "+f"(d[1]), "+f"(d[2]), "+f"(d[3])
        : "r"(a0), "r"(a1), "r"(a2), "r"(a3), "r"(b0), "r"(b1));
}

// ---- weight pre-split + packed-pair relayout ----
__global__ void w_setup(const float* __restrict__ W1, const float* __restrict__ W2) {
    int t = threadIdx.x;
    for (int i = t; i < 80*128; i += 256) {     // W1[k][n]
        int k = i >> 7, n = i & 127;
        float v = W1[i];
        float hi = __uint_as_float(tf32h(v));
        int kc = k >> 3, q = k & 3, s2 = (k >> 2) & 1;
        int idx = (kc*512 + n*4 + q)*2 + s2;
        g_w1ph[idx] = hi;
        g_w1pl[idx] = v - hi;
    }
    for (int i = t; i < 128*16; i += 256) {     // W2[k][n]
        int k = i >> 4, n = i & 15;
        float v = W2[i];
        float hi = __uint_as_float(tf32h(v));
        int kc = k >> 3, q = k & 3, s2 = (k >> 2) & 1;
        int idx = (kc*64 + n*4 + q)*2 + s2;
        g_w2ph[idx] = hi;
        g_w2pl[idx] = v - hi;
    }
}

// stage 48 row-segments (16ch x 3 rows, 66 halo cols) of a 64-px tile
__device__ __forceinline__ void stage_tile(const float* __restrict__ src,
                                           uint32_t sbase, int rb,
                                           int y, int x0, int wg, int lane)
{
    const int ym = (y == 0)    ? 0 : (y - 1);
    const int yp = (y == Hn-1) ? 0 : (y + 1);
    #pragma unroll 1
    for (int s = wg; s < 48; s += 4) {
        int c  = s / 3;
        int ri = s - c*3;
        int gy = (ri == 0) ? ym : ((ri == 1) ? y : yp);
        const float* gsrc = src + c*HWn + gy*Wn;
        uint32_t dbase = sbase + (uint32_t)(rb + s*RS2) * 4u;
        #pragma unroll
        for (int j0 = 0; j0 < 96; j0 += 32) {
            int j = j0 + lane;
            if (j < 66) {
                int gx = x0 - 1 + j;
                gx = (gx < 0)   ? 0 : gx;     // clamp low edge
                gx = (gx >= Wn) ? 0 : gx;     // wrap high edge
                cpa4(dbase + 4u*j, gsrc + gx);
            }
        }
    }
}

__global__ void __launch_bounds__(NTHREADS, 1)
slime_step_mma(const float* __restrict__ src, float* __restrict__ dst,
               const float* __restrict__ gb1, const float* __restrict__ gb2)
{
    extern __shared__ float sm[];
    const uint32_t sbase = smem_u32(sm);
    const int tid = threadIdx.x;
    const int w = tid >> 5, lane = tid & 31;
    const int gr = lane >> 2, q = lane & 3;
    const int g  = w >> 2;        // group 0/1
    const int wg = w & 3;         // warp within group
    const int barid = 1 + g;      // named barrier per group

    // ---- prologue (full block): packed weights + biases to SMEM ----
    {
        float4* d; const float4* s;
        d = (float4*)(sm + OFF_W1H); s = (const float4*)g_w1ph;
        #pragma unroll
        for (int i = 0; i < 10; i++) d[i*NTHREADS + tid] = s[i*NTHREADS + tid];
        d = (float4*)(sm + OFF_W1L); s = (const float4*)g_w1pl;
        #pragma unroll
        for (int i = 0; i < 10; i++) d[i*NTHREADS + tid] = s[i*NTHREADS + tid];
        d = (float4*)(sm + OFF_W2H); s = (const float4*)g_w2ph;
        #pragma unroll
        for (int i = 0; i < 2; i++) d[i*NTHREADS + tid] = s[i*NTHREADS + tid];
        d = (float4*)(sm + OFF_W2L); s = (const float4*)g_w2pl;
        #pragma unroll
        for (int i = 0; i < 2; i++) d[i*NTHREADS + tid] = s[i*NTHREADS + tid];
        if (tid < 128) sm[OFF_B1 + tid] = gb1[tid];
        if (tid < 16)  sm[OFF_B2 + tid] = gb2[tid];
    }
    __syncthreads();   // groups diverge after this point

    // ---- tile-invariant A-fragment offsets (relative to rows buffer) ----
    int foA[20];
    #pragma unroll
    for (int kc = 0; kc < 10; kc++)
        #pragma unroll
        for (int s2 = 0; s2 < 2; s2++) {
            int k = kc*8 + q + 4*s2;
            int dd = k >> 4, c = k & 15;
            int ri = (dd == 1) ? 0 : ((dd == 2) ? 2 : 1);
            int dx = (dd == 3) ? -1 : ((dd == 4) ? 1 : 0);
            foA[kc*2 + s2] = (c*3 + ri)*RS2 + 1 + dx;
        }

    // GEMM1: group = 1 row-group (64 rows) x 4 col-quarters
    const int C0 = wg * 32;
    // GEMM2: warp = 16 rows x 16 cols
    const int R2 = wg * 16;

    const float2* W1Hf = (const float2*)(sm + OFF_W1H);
    const float2* W1Lf = (const float2*)(sm + OFF_W1L);
    const float2* W2Hf = (const float2*)(sm + OFF_W2H);
    const float2* W2Lf = (const float2*)(sm + OFF_W2L);
    const float* b1s = sm + OFF_B1;
    const float* b2s = sm + OFF_B2;
    float* Hs = sm + OFF_H + g*HBUFSZ;

    const int t0 = blockIdx.x*2 + g;
    const int rb0 = OFF_R + (g*2 + 0)*RBUFSZ;
    const int rb1 = OFF_R + (g*2 + 1)*RBUFSZ;

    stage_tile(src, sbase, rb0, t0 >> 3, (t0 & 7) << 6, wg, lane);
    CP_COMMIT();
    CP_WAIT0();
    BARG(barid);

    int pb = 0;
    #pragma unroll 1
    for (int t = t0; t < NT2; t += TSTRIDE) {
        const int y = t >> 3, x0 = (t & 7) << 6;
        const int rb  = pb ? rb1 : rb0;
        const int rbn = pb ? rb0 : rb1;
        const float* rcur = sm + rb;

        const int tn = t + TSTRIDE;
        if (tn < NT2)
            stage_tile(src, sbase, rbn, tn >> 3, (tn & 7) << 6, wg, lane);
        CP_COMMIT();

        // ================= GEMM1: D1 = X @ W1 (+b1), 3xtf32 =================
        float acc[4][4][4];
        #pragma unroll
        for (int nt = 0; nt < 4; nt++) {
            float bz0 = b1s[C0 + nt*8 + 2*q];
            float bz1 = b1s[C0 + nt*8 + 2*q + 1];
            #pragma unroll
            for (int mt = 0; mt < 4; mt++) {
                acc[mt][nt][0] = bz0; acc[mt][nt][1] = bz1;
                acc[mt][nt][2] = bz0; acc[mt][nt][3] = bz1;
            }
        }
        #pragma unroll
        for (int kc = 0; kc < 10; kc++) {
            uint32_t ah[4][4], al[4][4];
            #pragma unroll
            for (int mt = 0; mt < 4; mt++) {
                int r = mt*16 + gr;
                float v0 = rcur[foA[kc*2+0] + r];
                float v1 = rcur[foA[kc*2+0] + r + 8];
                float v2 = rcur[foA[kc*2+1] + r];
                float v3 = rcur[foA[kc*2+1] + r + 8];
                ah[mt][0] = tf32h(v0); al[mt][0] = __float_as_uint(v0 - __uint_as_float(ah[mt][0]));
                ah[mt][1] = tf32h(v1); al[mt][1] = __float_as_uint(v1 - __uint_as_float(ah[mt][1]));
                ah[mt][2] = tf32h(v2); al[mt][2] = __float_as_uint(v2 - __uint_as_float(ah[mt][2]));
                ah[mt][3] = tf32h(v3); al[mt][3] = __float_as_uint(v3 - __uint_as_float(ah[mt][3]));
            }
            float2 bhv[4], blv[4];
            #pragma unroll
            for (int nt = 0; nt < 4; nt++) {
                int idx = kc*512 + (C0 + nt*8 + gr)*4 + q;
                bhv[nt] = W1Hf[idx];
                blv[nt] = W1Lf[idx];
            }
            #pragma unroll
            for (int nt = 0; nt < 4; nt++)
                #pragma unroll
                for (int mt = 0; mt < 4; mt++)
                    mma8(acc[mt][nt], ah[mt][0], ah[mt][1], ah[mt][2], ah[mt][3],
                         __float_as_uint(bhv[nt].x), __float_as_uint(bhv[nt].y));
            #pragma unroll
            for (int nt = 0; nt < 4; nt++)
                #pragma unroll
                for (int mt = 0; mt < 4; mt++)
                    mma8(acc[mt][nt], al[mt][0], al[mt][1], al[mt][2], al[mt][3],
                         __float_as_uint(bhv[nt].x), __float_as_uint(bhv[nt].y));
            #pragma unroll
            for (int nt = 0; nt < 4; nt++)
                #pragma unroll
                for (int mt = 0; mt < 4; mt++)
                    mma8(acc[mt][nt], ah[mt][0], ah[mt][1], ah[mt][2], ah[mt][3],
                         __float_as_uint(blv[nt].x), __float_as_uint(blv[nt].y));
        }
        // ---- H = relu(D1) ----
        #pragma unroll
        for (int mt = 0; mt < 4; mt++) {
            int r = mt*16 + gr;
            #pragma unroll
            for (int nt = 0; nt < 4; nt++) {
                int c = C0 + nt*8 + 2*q;
                float2 v0 = make_float2(fmaxf(acc[mt][nt][0], 0.0f), fmaxf(acc[mt][nt][1], 0.0f));
                float2 v1 = make_float2(fmaxf(acc[mt][nt][2], 0.0f), fmaxf(acc[mt][nt][3], 0.0f));
                *(float2*)&Hs[r*HS + c]     = v0;
                *(float2*)&Hs[(r+8)*HS + c] = v1;
            }
        }
        BARG(barid);

        // ================= GEMM2: D2 = H @ W2 (+b2), 3xtf32, K-split =================
        float da[2][4], db[2][4];
        #pragma unroll
        for (int nt = 0; nt < 2; nt++) {
            float bz0 = b2s[nt*8 + 2*q], bz1 = b2s[nt*8 + 2*q + 1];
            da[nt][0] = bz0; da[nt][1] = bz1; da[nt][2] = bz0; da[nt][3] = bz1;
            db[nt][0] = 0.f; db[nt][1] = 0.f; db[nt][2] = 0.f; db[nt][3] = 0.f;
        }
        #pragma unroll
        for (int kp = 0; kp < 8; kp++) {
            uint32_t aah[4], aal[4], bah[4], bal[4];
            {
                int r = R2 + gr;
                float v0 = Hs[r*HS     + kp*8 + q];
                float v1 = Hs[(r+8)*HS + kp*8 + q];
                float v2 = Hs[r*HS     + kp*8 + q + 4];
                float v3 = Hs[(r+8)*HS + kp*8 + q + 4];
                aah[0] = tf32h(v0); aal[0] = __float_as_uint(v0 - __uint_as_float(aah[0]));
                aah[1] = tf32h(v1); aal[1] = __float_as_uint(v1 - __uint_as_float(aah[1]));
                aah[2] = tf32h(v2); aal[2] = __float_as_uint(v2 - __uint_as_float(aah[2]));
                aah[3] = tf32h(v3); aal[3] = __float_as_uint(v3 - __uint_as_float(aah[3]));
                float w0 = Hs[r*HS     + (kp+8)*8 + q];
                float w1 = Hs[(r+8)*HS + (kp+8)*8 + q];
                float w2 = Hs[r*HS     + (kp+8)*8 + q + 4];
                float w3 = Hs[(r+8)*HS + (kp+8)*8 + q + 4];
                bah[0] = tf32h(w0); bal[0] = __float_as_uint(w0 - __uint_as_float(bah[0]));
                bah[1] = tf32h(w1); bal[1] = __float_as_uint(w1 - __uint_as_float(bah[1]));
                bah[2] = tf32h(w2); bal[2] = __float_as_uint(w2 - __uint_as_float(bah[2]));
                bah[3] = tf32h(w3); bal[3] = __float_as_uint(w3 - __uint_as_float(bah[3]));
            }
            #pragma unroll
            for (int nt = 0; nt < 2; nt++) {
                int ia = kp*64 + (nt*8 + gr)*4 + q;
                int ib = (kp+8)*64 + (nt*8 + gr)*4 + q;
                float2 wha = W2Hf[ia], wla = W2Lf[ia];
                float2 whb = W2Hf[ib], wlb = W2Lf[ib];
                mma8(da[nt], aah[0], aah[1], aah[2], aah[3], __float_as_uint(wha.x), __float_as_uint(wha.y));
                mma8(db[nt], bah[0], bah[1], bah[2], bah[3], __float_as_uint(whb.x), __float_as_uint(whb.y));
                mma8(da[nt], aal[0], aal[1], aal[2], aal[3], __float_as_uint(wha.x), __float_as_uint(wha.y));
                mma8(db[nt], bal[0], bal[1], bal[2], bal[3], __float_as_uint(whb.x), __float_as_uint(whb.y));
                mma8(da[nt], aah[0], aah[1], aah[2], aah[3], __float_as_uint(wla.x), __float_as_uint(wla.y));
                mma8(db[nt], bah[0], bah[1], bah[2], bah[3], __float_as_uint(wlb.x), __float_as_uint(wlb.y));
            }
        }

        // ---- output: s + delta (channel 0 snapshot-restored) ----
        {
            int px0  = R2 + gr;
            int pix0 = y*Wn + x0 + px0;
            #pragma unroll
            for (int nt = 0; nt < 2; nt++) {
                #pragma unroll
                for (int jj = 0; jj < 4; jj++) {
                    int c   = nt*8 + 2*q + (jj & 1);
                    int px  = px0  + ((jj >= 2) ? 8 : 0);
                    int pix = pix0 + ((jj >= 2) ? 8 : 0);
                    float center = rcur[(c*3 + 1)*RS2 + 1 + px];
                    float vout = (c == 0) ? center : (center + da[nt][jj] + db[nt][jj]);
                    dst[c*HWn + pix] = vout;
                }
            }
        }

        CP_WAIT0();
        BARG(barid);
        pb ^= 1;
    }
}

extern "C" void kernel_launch(void* const* d_in, const int* in_sizes, int n_in,
                              void* d_out, int out_size)
{
    const float* state = (const float*)d_in[0];
    const float* W1    = (const float*)d_in[1];
    const float* b1    = (const float*)d_in[2];
    const float* W2    = (const float*)d_in[3];
    const float* b2    = (const float*)d_in[4];
    float* out = (float*)d_out;

    cudaFuncSetAttribute(slime_step_mma,
                         cudaFuncAttributeMaxDynamicSharedMemorySize,
                         SMEM_FLOATS * (int)sizeof(float));

    float *bufA, *bufB;
    cudaGetSymbolAddress((void**)&bufA, g_bufA);
    cudaGetSymbolAddress((void**)&bufB, g_bufB);

    w_setup<<<1, 256>>>(W1, W2);

    const float* cur = state;
    for (int s = 0; s < NSTEPS; s++) {
        float* dstp = (s == NSTEPS-1) ? out : ((s & 1) ? bufB : bufA);
        slime_step_mma<<<GRIDX, NTHREADS, SMEM_FLOATS*sizeof(float)>>>(cur, dstp, b1, b2);
        cur = dstp;
    }
}

// round 11
// speedup vs baseline: 1.6109x; 1.6109x over previous
#include <cuda_runtime.h>
#include <cstdint>

#define Cn 16
#define Hn 512
#define Wn 512
#define HWn (Hn*Wn)
#define NSTEPS 8
#define GRIDX 152
#define NTHREADS 256
#define NTILES 2048
#define RSW 132            // rows segment stride (words)
#define HSW 68             // H packed stride (words)

// ---- smem word offsets ----
#define OFF_W1H 0                         // 5120 (uint2[5kc][128n][4q])
#define OFF_W1L 5120                      // 5120
#define OFF_W2H 10240                     // 1024 (uint2[8kc][16n][4q])
#define OFF_W2L 11264                     // 1024
#define OFF_B1  12288                     // 128
#define OFF_B2  12416                     // 16
#define OFF_R   12432                     // 2 x 64 segs x 132
#define RBUFSZ  (64*RSW)                  // 8448
#define OFF_HH  (OFF_R + 2*RBUFSZ)        // 29328 : 128 x 68 uint
#define OFF_HL  (OFF_HH + 128*HSW)        // 38032
#define SMEM_WORDS (OFF_HL + 128*HSW)     // 46736 -> 186944 B

__device__ float    g_bufA[Cn*HWn];
__device__ float    g_bufB[Cn*HWn];
__device__ uint32_t g_PhA[8*HWn];
__device__ uint32_t g_PlA[8*HWn];
__device__ uint32_t g_PhB[8*HWn];
__device__ uint32_t g_PlB[8*HWn];
__device__ uint2    g_w1h[2560];
__device__ uint2    g_w1l[2560];
__device__ uint2    g_w2h[512];
__device__ uint2    g_w2l[512];

__device__ __forceinline__ uint32_t packbf(float hi, float lo) {
    uint32_t d;
    asm("cvt.rn.bf16x2.f32 %0, %1, %2;" : "=r"(d) : "f"(hi), "f"(lo));
    return d;
}
__device__ __forceinline__ float hi_f(uint32_t p) { return __uint_as_float(p & 0xFFFF0000u); }
__device__ __forceinline__ float lo_f(uint32_t p) { return __uint_as_float(p << 16); }

__device__ __forceinline__ uint32_t smem_u32(const void* p) {
    uint32_t a;
    asm("{ .reg .u64 t; cvta.to.shared.u64 t, %1; cvt.u32.u64 %0, t; }" : "=r"(a) : "l"(p));
    return a;
}
__device__ __forceinline__ void cpa4(uint32_t d, const void* g) {
    asm volatile("cp.async.ca.shared.global [%0], [%1], 4;" :: "r"(d), "l"(g));
}
#define CP_COMMIT() asm volatile("cp.async.commit_group;" ::: "memory")
#define CP_WAIT0()  asm volatile("cp.async.wait_group 0;" ::: "memory")

__device__ __forceinline__ void mma16(float* d,
    uint32_t a0, uint32_t a1, uint32_t a2, uint32_t a3,
    uint32_t b0, uint32_t b1)
{
    asm volatile(
        "mma.sync.aligned.m16n8k16.row.col.f32.bf16.bf16.f32 "
        "{%0,%1,%2,%3}, {%4,%5,%6,%7}, {%8,%9}, {%0,%1,%2,%3};"
        : "+f"(d[0]), "+f"(d[1]), "+f"(d[2]), "+f"(d[3])
        : "r"(a0), "r"(a1), "r"(a2), "r"(a3), "r"(b0), "r"(b1));
}

// ---- weight bf16-split + packed-pair relayout ----
__global__ void w_setup(const float* __restrict__ W1, const float* __restrict__ W2) {
    int t = threadIdx.x;
    for (int i = t; i < 2560; i += 256) {        // W1[k][n] row-major, k<80
        int kc = i >> 9, rem = i & 511;
        int n = rem >> 2, q = rem & 3;
        int k0 = kc*16 + 2*q;
        float v0 = W1[(k0  )*128 + n], v1 = W1[(k0+1)*128 + n];
        float v8 = W1[(k0+8)*128 + n], v9 = W1[(k0+9)*128 + n];
        uint32_t h0 = packbf(v1, v0), h1 = packbf(v9, v8);
        uint32_t l0 = packbf(v1 - hi_f(h0), v0 - lo_f(h0));
        uint32_t l1 = packbf(v9 - hi_f(h1), v8 - lo_f(h1));
        g_w1h[i] = make_uint2(h0, h1);
        g_w1l[i] = make_uint2(l0, l1);
    }
    for (int i = t; i < 512; i += 256) {         // W2[k][n], k<128
        int kc = i >> 6, rem = i & 63;
        int n = rem >> 2, q = rem & 3;
        int k0 = kc*16 + 2*q;
        float v0 = W2[(k0  )*16 + n], v1 = W2[(k0+1)*16 + n];
        float v8 = W2[(k0+8)*16 + n], v9 = W2[(k0+9)*16 + n];
        uint32_t h0 = packbf(v1, v0), h1 = packbf(v9, v8);
        uint32_t l0 = packbf(v1 - hi_f(h0), v0 - lo_f(h0));
        uint32_t l1 = packbf(v9 - hi_f(h1), v8 - lo_f(h1));
        g_w2h[i] = make_uint2(h0, h1);
        g_w2l[i] = make_uint2(l0, l1);
    }
}

// ---- one-time: build packed channel-pair planes from input state ----
__global__ void pack_state(const float* __restrict__ s,
                           uint32_t* __restrict__ Ph, uint32_t* __restrict__ Pl) {
    int i = blockIdx.x*256 + threadIdx.x;        // i = pc*HW + pix
    int pc = i >> 18, pix = i & (HWn-1);
    float v0 = s[(2*pc  )*HWn + pix];
    float v1 = s[(2*pc+1)*HWn + pix];
    uint32_t ph = packbf(v1, v0);
    uint32_t pl = packbf(v1 - hi_f(ph), v0 - lo_f(ph));
    Ph[i] = ph;
    Pl[i] = pl;
}

// stage one tile: 48 packed segs (2 planes x 8 pc x 3 rows, halo) + 16 center f32 segs
__device__ __forceinline__ void stage_tile(const float* __restrict__ state,
                                           const uint32_t* __restrict__ Ph,
                                           const uint32_t* __restrict__ Pl,
                                           uint32_t sbase, int rb,
                                           int y, int x0, int w, int lane)
{
    const int ym = (y == 0)    ? 0 : (y - 1);
    const int yp = (y == Hn-1) ? 0 : (y + 1);
    #pragma unroll 1
    for (int s = w; s < 64; s += 8) {
        uint32_t dbase = sbase + (uint32_t)(rb + s*RSW) * 4u;
        if (s < 48) {
            int plane = (s >= 24);
            int t2 = s - plane*24;
            int pc = t2 / 3, ri = t2 - pc*3;
            int gy = (ri == 0) ? ym : ((ri == 1) ? y : yp);
            const uint32_t* gsrc = (plane ? Pl : Ph) + pc*HWn + gy*Wn;
            #pragma unroll
            for (int j0 = 0; j0 < 160; j0 += 32) {
                int j = j0 + lane;
                if (j < 130) {
                    int gx = x0 - 1 + j;
                    gx = (gx < 0)   ? 0 : gx;   // clamp low edge
                    gx = (gx >= Wn) ? 0 : gx;   // wrap high edge
                    cpa4(dbase + 4u*j, gsrc + gx);
                }
            }
        } else {
            int c = s - 48;
            const float* gsrc = state + c*HWn + y*Wn + x0;
            #pragma unroll
            for (int j0 = 0; j0 < 128; j0 += 32)
                cpa4(dbase + 4u*(1 + j0 + lane), gsrc + j0 + lane);
        }
    }
}

__global__ void __launch_bounds__(NTHREADS, 1)
slime_step_mma(const float* __restrict__ src,
               const uint32_t* __restrict__ srcPh, const uint32_t* __restrict__ srcPl,
               float* __restrict__ dst,
               uint32_t* __restrict__ dstPh, uint32_t* __restrict__ dstPl,
               const float* __restrict__ gb1, const float* __restrict__ gb2)
{
    extern __shared__ float sm[];
    const uint32_t sbase = smem_u32(sm);
    const int tid = threadIdx.x;
    const int w = tid >> 5, lane = tid & 31;
    const int gr = lane >> 2, q = lane & 3;

    // ---- prologue: packed weights + biases to SMEM ----
    {
        uint4* d; const uint4* s;
        d = (uint4*)(sm + OFF_W1H); s = (const uint4*)g_w1h;
        #pragma unroll
        for (int i = 0; i < 5; i++) d[i*NTHREADS + tid] = s[i*NTHREADS + tid];
        d = (uint4*)(sm + OFF_W1L); s = (const uint4*)g_w1l;
        #pragma unroll
        for (int i = 0; i < 5; i++) d[i*NTHREADS + tid] = s[i*NTHREADS + tid];
        ((uint4*)(sm + OFF_W2H))[tid] = ((const uint4*)g_w2h)[tid];
        ((uint4*)(sm + OFF_W2L))[tid] = ((const uint4*)g_w2l)[tid];
        if (tid < 128) sm[OFF_B1 + tid] = gb1[tid];
        if (tid < 16)  sm[OFF_B2 + tid] = gb2[tid];
    }

    // ---- tile-invariant A offsets: dir kc -> (ri,dx); pair pc = q / q+4 ----
    int foH[10];
    {
        const int riA[5] = {1, 0, 2, 1, 1};
        const int dxA[5] = {0, 0, 0, -1, 1};
        #pragma unroll
        for (int kc = 0; kc < 5; kc++) {
            #pragma unroll
            for (int p = 0; p < 2; p++)
                foH[kc*2+p] = ((q + 4*p)*3 + riA[kc])*RSW + 1 + dxA[kc];
        }
    }

    // GEMM1: 8 warps = 2 row-halves x 4 col-quarters
    const int R0 = (w >> 2) * 64, C0 = (w & 3) * 32;
    // GEMM2: warp = 16 rows x 16 cols
    const int R2 = w * 16;

    const uint2* W1Hu = (const uint2*)(sm + OFF_W1H);
    const uint2* W1Lu = (const uint2*)(sm + OFF_W1L);
    const uint2* W2Hu = (const uint2*)(sm + OFF_W2H);
    const uint2* W2Lu = (const uint2*)(sm + OFF_W2L);
    const float* b1s = sm + OFF_B1;
    const float* b2s = sm + OFF_B2;
    uint32_t* Hhu = (uint32_t*)(sm + OFF_HH);
    uint32_t* Hlu = (uint32_t*)(sm + OFF_HL);

    const int t0 = blockIdx.x;
    stage_tile(src, srcPh, srcPl, sbase, OFF_R, t0 >> 2, (t0 & 3) << 7, w, lane);
    CP_COMMIT();
    CP_WAIT0();
    __syncthreads();

    int pb = 0;
    #pragma unroll 1
    for (int t = t0; t < NTILES; t += GRIDX) {
        const int y = t >> 2, x0 = (t & 3) << 7;
        const int rb  = OFF_R + (pb ? RBUFSZ : 0);
        const int rbn = OFF_R + (pb ? 0 : RBUFSZ);
        const uint32_t* ru = (const uint32_t*)(sm + rb);
        const float*    rf = sm + rb;

        const int tn = t + GRIDX;
        if (tn < NTILES)
            stage_tile(src, srcPh, srcPl, sbase, rbn, tn >> 2, (tn & 3) << 7, w, lane);
        CP_COMMIT();

        // ============ GEMM1: D1 = X @ W1 (+b1), bf16 3-product ============
        float acc[4][4][4];
        #pragma unroll
        for (int nt = 0; nt < 4; nt++) {
            float bz0 = b1s[C0 + nt*8 + 2*q];
            float bz1 = b1s[C0 + nt*8 + 2*q + 1];
            #pragma unroll
            for (int mt = 0; mt < 4; mt++) {
                acc[mt][nt][0] = bz0; acc[mt][nt][1] = bz1;
                acc[mt][nt][2] = bz0; acc[mt][nt][3] = bz1;
            }
        }
        #pragma unroll
        for (int kc = 0; kc < 5; kc++) {
            const int o0 = foH[kc*2+0], o1 = foH[kc*2+1];
            uint32_t ah[4][4], al[4][4];
            #pragma unroll
            for (int mt = 0; mt < 4; mt++) {
                int r = R0 + mt*16 + gr;
                ah[mt][0] = ru[o0 + r];        al[mt][0] = ru[o0 + 3168 + r];
                ah[mt][1] = ru[o0 + r + 8];    al[mt][1] = ru[o0 + 3168 + r + 8];
                ah[mt][2] = ru[o1 + r];        al[mt][2] = ru[o1 + 3168 + r];
                ah[mt][3] = ru[o1 + r + 8];    al[mt][3] = ru[o1 + 3168 + r + 8];
            }
            uint2 bh[4], bl[4];
            #pragma unroll
            for (int nt = 0; nt < 4; nt++) {
                int idx = kc*512 + (C0 + nt*8 + gr)*4 + q;
                bh[nt] = W1Hu[idx];
                bl[nt] = W1Lu[idx];
            }
            #pragma unroll
            for (int nt = 0; nt < 4; nt++)
                #pragma unroll
                for (int mt = 0; mt < 4; mt++)
                    mma16(acc[mt][nt], ah[mt][0], ah[mt][1], ah[mt][2], ah[mt][3], bh[nt].x, bh[nt].y);
            #pragma unroll
            for (int nt = 0; nt < 4; nt++)
                #pragma unroll
                for (int mt = 0; mt < 4; mt++)
                    mma16(acc[mt][nt], al[mt][0], al[mt][1], al[mt][2], al[mt][3], bh[nt].x, bh[nt].y);
            #pragma unroll
            for (int nt = 0; nt < 4; nt++)
                #pragma unroll
                for (int mt = 0; mt < 4; mt++)
                    mma16(acc[mt][nt], ah[mt][0], ah[mt][1], ah[mt][2], ah[mt][3], bl[nt].x, bl[nt].y);
        }
        // ---- epilogue: H = relu(D1), packed bf16 hi/lo ----
        #pragma unroll
        for (int mt = 0; mt < 4; mt++) {
            int r = R0 + mt*16 + gr;
            #pragma unroll
            for (int nt = 0; nt < 4; nt++) {
                int pcc = (C0 >> 1) + nt*4 + q;
                float h0 = fmaxf(acc[mt][nt][0], 0.0f);
                float h1 = fmaxf(acc[mt][nt][1], 0.0f);
                float h2 = fmaxf(acc[mt][nt][2], 0.0f);
                float h3 = fmaxf(acc[mt][nt][3], 0.0f);
                uint32_t p0 = packbf(h1, h0);
                uint32_t p1 = packbf(h3, h2);
                Hhu[r*HSW + pcc]     = p0;
                Hhu[(r+8)*HSW + pcc] = p1;
                Hlu[r*HSW + pcc]     = packbf(h1 - hi_f(p0), h0 - lo_f(p0));
                Hlu[(r+8)*HSW + pcc] = packbf(h3 - hi_f(p1), h2 - lo_f(p1));
            }
        }
        __syncthreads();

        // ============ GEMM2: D2 = H @ W2 (+b2), bf16 3-product, K-split ============
        float da[2][4], db[2][4];
        #pragma unroll
        for (int nt = 0; nt < 2; nt++) {
            float bz0 = b2s[nt*8 + 2*q], bz1 = b2s[nt*8 + 2*q + 1];
            da[nt][0] = bz0; da[nt][1] = bz1; da[nt][2] = bz0; da[nt][3] = bz1;
            db[nt][0] = 0.f; db[nt][1] = 0.f; db[nt][2] = 0.f; db[nt][3] = 0.f;
        }
        #pragma unroll
        for (int kp = 0; kp < 4; kp++) {
            int r = R2 + gr;
            int ca = kp*8 + q, cb = (kp+4)*8 + q;
            uint32_t Aah[4], Aal[4], Bah[4], Bal[4];
            Aah[0] = Hhu[r*HSW + ca];       Aal[0] = Hlu[r*HSW + ca];
            Aah[1] = Hhu[(r+8)*HSW + ca];   Aal[1] = Hlu[(r+8)*HSW + ca];
            Aah[2] = Hhu[r*HSW + ca+4];     Aal[2] = Hlu[r*HSW + ca+4];
            Aah[3] = Hhu[(r+8)*HSW + ca+4]; Aal[3] = Hlu[(r+8)*HSW + ca+4];
            Bah[0] = Hhu[r*HSW + cb];       Bal[0] = Hlu[r*HSW + cb];
            Bah[1] = Hhu[(r+8)*HSW + cb];   Bal[1] = Hlu[(r+8)*HSW + cb];
            Bah[2] = Hhu[r*HSW + cb+4];     Bal[2] = Hlu[r*HSW + cb+4];
            Bah[3] = Hhu[(r+8)*HSW + cb+4]; Bal[3] = Hlu[(r+8)*HSW + cb+4];
            #pragma unroll
            for (int nt = 0; nt < 2; nt++) {
                int ia = kp*64 + (nt*8 + gr)*4 + q;
                int ib = (kp+4)*64 + (nt*8 + gr)*4 + q;
                uint2 wha = W2Hu[ia], wla = W2Lu[ia];
                uint2 whb = W2Hu[ib], wlb = W2Lu[ib];
                mma16(da[nt], Aah[0], Aah[1], Aah[2], Aah[3], wha.x, wha.y);
                mma16(db[nt], Bah[0], Bah[1], Bah[2], Bah[3], whb.x, whb.y);
                mma16(da[nt], Aal[0], Aal[1], Aal[2], Aal[3], wha.x, wha.y);
                mma16(db[nt], Bal[0], Bal[1], Bal[2], Bal[3], whb.x, whb.y);
                mma16(da[nt], Aah[0], Aah[1], Aah[2], Aah[3], wla.x, wla.y);
                mma16(db[nt], Bah[0], Bah[1], Bah[2], Bah[3], wlb.x, wlb.y);
            }
        }

        // ---- output: f32 state + packed hi/lo planes (ch0 snapshot-restored) ----
        {
            int px0  = R2 + gr;
            int pix0 = y*Wn + x0 + px0;
            #pragma unroll
            for (int nt = 0; nt < 2; nt++) {
                int c0 = nt*8 + 2*q;
                int pcb = (c0 >> 1);
                #pragma unroll
                for (int h = 0; h < 2; h++) {
                    int px  = px0  + 8*h;
                    int pix = pix0 + 8*h;
                    float ctr0 = rf[(48 + c0    )*RSW + 1 + px];
                    float ctr1 = rf[(48 + c0 + 1)*RSW + 1 + px];
                    float d0 = da[nt][2*h]   + db[nt][2*h];
                    float d1 = da[nt][2*h+1] + db[nt][2*h+1];
                    float out0 = (c0 == 0) ? ctr0 : (ctr0 + d0);
                    float out1 = ctr1 + d1;
                    dst[c0*HWn + pix]       = out0;
                    dst[(c0+1)*HWn + pix]   = out1;
                    uint32_t ph = packbf(out1, out0);
                    dstPh[pcb*HWn + pix] = ph;
                    dstPl[pcb*HWn + pix] = packbf(out1 - hi_f(ph), out0 - lo_f(ph));
                }
            }
        }

        CP_WAIT0();
        __syncthreads();
        pb ^= 1;
    }
}

extern "C" void kernel_launch(void* const* d_in, const int* in_sizes, int n_in,
                              void* d_out, int out_size)
{
    const float* state = (const float*)d_in[0];
    const float* W1    = (const float*)d_in[1];
    const float* b1    = (const float*)d_in[2];
    const float* W2    = (const float*)d_in[3];
    const float* b2    = (const float*)d_in[4];
    float* out = (float*)d_out;

    cudaFuncSetAttribute(slime_step_mma,
                         cudaFuncAttributeMaxDynamicSharedMemorySize,
                         SMEM_WORDS * (int)sizeof(float));

    float *bufA, *bufB;
    uint32_t *PhA, *PlA, *PhB, *PlB;
    cudaGetSymbolAddress((void**)&bufA, g_bufA);
    cudaGetSymbolAddress((void**)&bufB, g_bufB);
    cudaGetSymbolAddress((void**)&PhA, g_PhA);
    cudaGetSymbolAddress((void**)&PlA, g_PlA);
    cudaGetSymbolAddress((void**)&PhB, g_PhB);
    cudaGetSymbolAddress((void**)&PlB, g_PlB);

    w_setup<<<1, 256>>>(W1, W2);
    pack_state<<<(8*HWn)/256, 256>>>(state, PhA, PlA);

    const float* cur = state;
    for (int s = 0; s < NSTEPS; s++) {
        float* dstp = (s == NSTEPS-1) ? out : ((s & 1) ? bufB : bufA);
        const uint32_t* sPh = (s & 1) ? PhB : PhA;
        const uint32_t* sPl = (s & 1) ? PlB : PlA;
        uint32_t* dPh = (s & 1) ? PhA : PhB;
        uint32_t* dPl = (s & 1) ? PlA : PlB;
        slime_step_mma<<<GRIDX, NTHREADS, SMEM_WORDS*sizeof(float)>>>(
            cur, sPh, sPl, dstp, dPh, dPl, b1, b2);
        cur = dstp;
    }
}

// round 12
// speedup vs baseline: 1.7134x; 1.0636x over previous
#include <cuda_runtime.h>
#include <cstdint>

#define Cn 16
#define Hn 512
#define Wn 512
#define HWn (Hn*Wn)
#define NSTEPS 8
#define GRIDX 152
#define NTHREADS 256
#define NTILES 2048
#define RSW 132            // rows segment stride (words)
#define HSW 68             // H packed stride (words)
#define RPLO (24*RSW)      // lo-plane offset within rows buffer (3168)

// ---- smem word offsets ----
#define OFF_W1H 0                         // 5120 (uint2[5kc][128n][4q])
#define OFF_W1L 5120
#define OFF_W2H 10240                     // 1024 (uint2[8kc][16n][4q])
#define OFF_W2L 11264
#define OFF_B1  12288
#define OFF_B2  12416
#define OFF_R   12432                     // 2 x 48 segs x 132
#define RBUFSZ  (48*RSW)                  // 6336
#define OFF_HH  (OFF_R + 2*RBUFSZ)        // 25104
#define OFF_HL  (OFF_HH + 128*HSW)
#define SMEM_WORDS (OFF_HL + 128*HSW)     // 42512 -> 170048 B

__device__ float    g_bufF[Cn*HWn];       // never read; dummy f32 dst for warm steps
__device__ uint32_t g_PhA[8*HWn];
__device__ uint32_t g_PlA[8*HWn];
__device__ uint32_t g_PhB[8*HWn];
__device__ uint32_t g_PlB[8*HWn];
__device__ uint2    g_w1h[2560];
__device__ uint2    g_w1l[2560];
__device__ uint2    g_w2h[512];
__device__ uint2    g_w2l[512];

__device__ __forceinline__ uint32_t packbf(float hi, float lo) {
    uint32_t d;
    asm("cvt.rn.bf16x2.f32 %0, %1, %2;" : "=r"(d) : "f"(hi), "f"(lo));
    return d;
}
__device__ __forceinline__ float hi_f(uint32_t p) { return __uint_as_float(p & 0xFFFF0000u); }
__device__ __forceinline__ float lo_f(uint32_t p) { return __uint_as_float(p << 16); }

__device__ __forceinline__ uint32_t smem_u32(const void* p) {
    uint32_t a;
    asm("{ .reg .u64 t; cvta.to.shared.u64 t, %1; cvt.u32.u64 %0, t; }" : "=r"(a) : "l"(p));
    return a;
}
__device__ __forceinline__ void cpa4(uint32_t d, const void* g) {
    asm volatile("cp.async.ca.shared.global [%0], [%1], 4;" :: "r"(d), "l"(g));
}
#define CP_COMMIT() asm volatile("cp.async.commit_group;" ::: "memory")
#define CP_WAIT0()  asm volatile("cp.async.wait_group 0;" ::: "memory")

__device__ __forceinline__ void mma16(float* d,
    uint32_t a0, uint32_t a1, uint32_t a2, uint32_t a3,
    uint32_t b0, uint32_t b1)
{
    asm volatile(
        "mma.sync.aligned.m16n8k16.row.col.f32.bf16.bf16.f32 "
        "{%0,%1,%2,%3}, {%4,%5,%6,%7}, {%8,%9}, {%0,%1,%2,%3};"
        : "+f"(d[0]), "+f"(d[1]), "+f"(d[2]), "+f"(d[3])
        : "r"(a0), "r"(a1), "r"(a2), "r"(a3), "r"(b0), "r"(b1));
}

// ---- weight bf16-split + packed-pair relayout ----
__global__ void w_setup(const float* __restrict__ W1, const float* __restrict__ W2) {
    int t = threadIdx.x;
    for (int i = t; i < 2560; i += 256) {        // W1[k][n], k<80
        int kc = i >> 9, rem = i & 511;
        int n = rem >> 2, q = rem & 3;
        int k0 = kc*16 + 2*q;
        float v0 = W1[(k0  )*128 + n], v1 = W1[(k0+1)*128 + n];
        float v8 = W1[(k0+8)*128 + n], v9 = W1[(k0+9)*128 + n];
        uint32_t h0 = packbf(v1, v0), h1 = packbf(v9, v8);
        g_w1h[i] = make_uint2(h0, h1);
        g_w1l[i] = make_uint2(packbf(v1 - hi_f(h0), v0 - lo_f(h0)),
                              packbf(v9 - hi_f(h1), v8 - lo_f(h1)));
    }
    for (int i = t; i < 512; i += 256) {         // W2[k][n], k<128
        int kc = i >> 6, rem = i & 63;
        int n = rem >> 2, q = rem & 3;
        int k0 = kc*16 + 2*q;
        float v0 = W2[(k0  )*16 + n], v1 = W2[(k0+1)*16 + n];
        float v8 = W2[(k0+8)*16 + n], v9 = W2[(k0+9)*16 + n];
        uint32_t h0 = packbf(v1, v0), h1 = packbf(v9, v8);
        g_w2h[i] = make_uint2(h0, h1);
        g_w2l[i] = make_uint2(packbf(v1 - hi_f(h0), v0 - lo_f(h0)),
                              packbf(v9 - hi_f(h1), v8 - lo_f(h1)));
    }
}

// ---- one-time: build packed channel-pair planes from input f32 state ----
__global__ void pack_state(const float* __restrict__ s,
                           uint32_t* __restrict__ Ph, uint32_t* __restrict__ Pl) {
    int i = blockIdx.x*256 + threadIdx.x;
    int pc = i >> 18, pix = i & (HWn-1);
    float v0 = s[(2*pc  )*HWn + pix];
    float v1 = s[(2*pc+1)*HWn + pix];
    uint32_t ph = packbf(v1, v0);
    Ph[i] = ph;
    Pl[i] = packbf(v1 - hi_f(ph), v0 - lo_f(ph));
}

// stage one tile: 48 packed segs (2 planes x 8 pc x 3 rows), halo cols
__device__ __forceinline__ void stage_tile(const uint32_t* __restrict__ Ph,
                                           const uint32_t* __restrict__ Pl,
                                           uint32_t sbase, int rb,
                                           int y, int x0, int w, int lane)
{
    const int ym = (y == 0)    ? 0 : (y - 1);
    const int yp = (y == Hn-1) ? 0 : (y + 1);
    #pragma unroll 1
    for (int s = w; s < 48; s += 8) {
        uint32_t dbase = sbase + (uint32_t)(rb + s*RSW) * 4u;
        int plane = (s >= 24);
        int t2 = s - plane*24;
        int pc = t2 / 3, ri = t2 - pc*3;
        int gy = (ri == 0) ? ym : ((ri == 1) ? y : yp);
        const uint32_t* gsrc = (plane ? Pl : Ph) + pc*HWn + gy*Wn;
        #pragma unroll
        for (int j0 = 0; j0 < 160; j0 += 32) {
            int j = j0 + lane;
            if (j < 130) {
                int gx = x0 - 1 + j;
                gx = (gx < 0)   ? 0 : gx;   // clamp low edge
                gx = (gx >= Wn) ? 0 : gx;   // wrap high edge
                cpa4(dbase + 4u*j, gsrc + gx);
            }
        }
    }
}

__global__ void __launch_bounds__(NTHREADS, 1)
slime_step_mma(const uint32_t* __restrict__ srcPh, const uint32_t* __restrict__ srcPl,
               uint32_t* __restrict__ dstPh, uint32_t* __restrict__ dstPl,
               float* __restrict__ dstF, int writeF32,
               const float* __restrict__ gb1, const float* __restrict__ gb2)
{
    extern __shared__ float sm[];
    const uint32_t sbase = smem_u32(sm);
    const int tid = threadIdx.x;
    const int w = tid >> 5, lane = tid & 31;
    const int gr = lane >> 2, q = lane & 3;

    // ---- prologue: packed weights + biases to SMEM ----
    {
        uint4* d; const uint4* s;
        d = (uint4*)(sm + OFF_W1H); s = (const uint4*)g_w1h;
        #pragma unroll
        for (int i = 0; i < 5; i++) d[i*NTHREADS + tid] = s[i*NTHREADS + tid];
        d = (uint4*)(sm + OFF_W1L); s = (const uint4*)g_w1l;
        #pragma unroll
        for (int i = 0; i < 5; i++) d[i*NTHREADS + tid] = s[i*NTHREADS + tid];
        ((uint4*)(sm + OFF_W2H))[tid] = ((const uint4*)g_w2h)[tid];
        ((uint4*)(sm + OFF_W2L))[tid] = ((const uint4*)g_w2l)[tid];
        if (tid < 128) sm[OFF_B1 + tid] = gb1[tid];
        if (tid < 16)  sm[OFF_B2 + tid] = gb2[tid];
    }

    // ---- tile-invariant A offsets (packed planes): dir kc -> (ri,dx) ----
    int foH[10];
    {
        const int riA[5] = {1, 0, 2, 1, 1};
        const int dxA[5] = {0, 0, 0, -1, 1};
        #pragma unroll
        for (int kc = 0; kc < 5; kc++)
            #pragma unroll
            for (int p = 0; p < 2; p++)
                foH[kc*2+p] = ((q + 4*p)*3 + riA[kc])*RSW + 1 + dxA[kc];
    }

    const int R0 = (w >> 2) * 64, C0 = (w & 3) * 32;   // GEMM1 (2,4)
    const int R2 = w * 16;                              // GEMM2 16x16

    const uint2* W1Hu = (const uint2*)(sm + OFF_W1H);
    const uint2* W1Lu = (const uint2*)(sm + OFF_W1L);
    const uint2* W2Hu = (const uint2*)(sm + OFF_W2H);
    const uint2* W2Lu = (const uint2*)(sm + OFF_W2L);
    const float* b1s = sm + OFF_B1;
    const float* b2s = sm + OFF_B2;
    uint32_t* Hhu = (uint32_t*)(sm + OFF_HH);
    uint32_t* Hlu = (uint32_t*)(sm + OFF_HL);

    const int t0 = blockIdx.x;
    stage_tile(srcPh, srcPl, sbase, OFF_R, t0 >> 2, (t0 & 3) << 7, w, lane);
    CP_COMMIT();
    CP_WAIT0();
    __syncthreads();

    // ---- hoist tile-invariant W2-hi fragments into registers ----
    uint2 w2h_r[4][2];
    #pragma unroll
    for (int kp = 0; kp < 4; kp++) {
        w2h_r[kp][0] = W2Hu[kp*64 + (0*8 + gr)*4 + q];
        w2h_r[kp][1] = W2Hu[kp*64 + (1*8 + gr)*4 + q];
    }
    uint2 w2hb_r[4][2];
    #pragma unroll
    for (int kp = 0; kp < 4; kp++) {
        w2hb_r[kp][0] = W2Hu[(kp+4)*64 + (0*8 + gr)*4 + q];
        w2hb_r[kp][1] = W2Hu[(kp+4)*64 + (1*8 + gr)*4 + q];
    }

    int pb = 0;
    #pragma unroll 1
    for (int t = t0; t < NTILES; t += GRIDX) {
        const int y = t >> 2, x0 = (t & 3) << 7;
        const int rb  = OFF_R + (pb ? RBUFSZ : 0);
        const int rbn = OFF_R + (pb ? 0 : RBUFSZ);
        const uint32_t* ru = (const uint32_t*)(sm + rb);

        const int tn = t + GRIDX;
        if (tn < NTILES)
            stage_tile(srcPh, srcPl, sbase, rbn, tn >> 2, (tn & 3) << 7, w, lane);
        CP_COMMIT();

        // ============ GEMM1: D1 = X @ W1 (+b1), bf16 3-product ============
        float acc[4][4][4];
        #pragma unroll
        for (int nt = 0; nt < 4; nt++) {
            float bz0 = b1s[C0 + nt*8 + 2*q];
            float bz1 = b1s[C0 + nt*8 + 2*q + 1];
            #pragma unroll
            for (int mt = 0; mt < 4; mt++) {
                acc[mt][nt][0] = bz0; acc[mt][nt][1] = bz1;
                acc[mt][nt][2] = bz0; acc[mt][nt][3] = bz1;
            }
        }
        #pragma unroll
        for (int kc = 0; kc < 5; kc++) {
            const int o0 = foH[kc*2+0], o1 = foH[kc*2+1];
            uint32_t ah[4][4], al[4][4];
            #pragma unroll
            for (int mt = 0; mt < 4; mt++) {
                int r = R0 + mt*16 + gr;
                ah[mt][0] = ru[o0 + r];        al[mt][0] = ru[o0 + RPLO + r];
                ah[mt][1] = ru[o0 + r + 8];    al[mt][1] = ru[o0 + RPLO + r + 8];
                ah[mt][2] = ru[o1 + r];        al[mt][2] = ru[o1 + RPLO + r];
                ah[mt][3] = ru[o1 + r + 8];    al[mt][3] = ru[o1 + RPLO + r + 8];
            }
            uint2 bh[4], bl[4];
            #pragma unroll
            for (int nt = 0; nt < 4; nt++) {
                int idx = kc*512 + (C0 + nt*8 + gr)*4 + q;
                bh[nt] = W1Hu[idx];
                bl[nt] = W1Lu[idx];
            }
            #pragma unroll
            for (int nt = 0; nt < 4; nt++)
                #pragma unroll
                for (int mt = 0; mt < 4; mt++)
                    mma16(acc[mt][nt], ah[mt][0], ah[mt][1], ah[mt][2], ah[mt][3], bh[nt].x, bh[nt].y);
            #pragma unroll
            for (int nt = 0; nt < 4; nt++)
                #pragma unroll
                for (int mt = 0; mt < 4; mt++)
                    mma16(acc[mt][nt], al[mt][0], al[mt][1], al[mt][2], al[mt][3], bh[nt].x, bh[nt].y);
            #pragma unroll
            for (int nt = 0; nt < 4; nt++)
                #pragma unroll
                for (int mt = 0; mt < 4; mt++)
                    mma16(acc[mt][nt], ah[mt][0], ah[mt][1], ah[mt][2], ah[mt][3], bl[nt].x, bl[nt].y);
        }
        // ---- epilogue: H = relu(D1), packed bf16 hi/lo ----
        #pragma unroll
        for (int mt = 0; mt < 4; mt++) {
            int r = R0 + mt*16 + gr;
            #pragma unroll
            for (int nt = 0; nt < 4; nt++) {
                int pcc = (C0 >> 1) + nt*4 + q;
                float h0 = fmaxf(acc[mt][nt][0], 0.0f);
                float h1 = fmaxf(acc[mt][nt][1], 0.0f);
                float h2 = fmaxf(acc[mt][nt][2], 0.0f);
                float h3 = fmaxf(acc[mt][nt][3], 0.0f);
                uint32_t p0 = packbf(h1, h0);
                uint32_t p1 = packbf(h3, h2);
                Hhu[r*HSW + pcc]     = p0;
                Hhu[(r+8)*HSW + pcc] = p1;
                Hlu[r*HSW + pcc]     = packbf(h1 - hi_f(p0), h0 - lo_f(p0));
                Hlu[(r+8)*HSW + pcc] = packbf(h3 - hi_f(p1), h2 - lo_f(p1));
            }
        }
        __syncthreads();

        // ============ GEMM2: D2 = H @ W2 (+b2), bf16 3-product, K-split ============
        float da[2][4], db[2][4];
        #pragma unroll
        for (int nt = 0; nt < 2; nt++) {
            float bz0 = b2s[nt*8 + 2*q], bz1 = b2s[nt*8 + 2*q + 1];
            da[nt][0] = bz0; da[nt][1] = bz1; da[nt][2] = bz0; da[nt][3] = bz1;
            db[nt][0] = 0.f; db[nt][1] = 0.f; db[nt][2] = 0.f; db[nt][3] = 0.f;
        }
        #pragma unroll
        for (int kp = 0; kp < 4; kp++) {
            int r = R2 + gr;
            int ca = kp*8 + q, cb = (kp+4)*8 + q;
            uint32_t Aah[4], Aal[4], Bah[4], Bal[4];
            Aah[0] = Hhu[r*HSW + ca];       Aal[0] = Hlu[r*HSW + ca];
            Aah[1] = Hhu[(r+8)*HSW + ca];   Aal[1] = Hlu[(r+8)*HSW + ca];
            Aah[2] = Hhu[r*HSW + ca+4];     Aal[2] = Hlu[r*HSW + ca+4];
            Aah[3] = Hhu[(r+8)*HSW + ca+4]; Aal[3] = Hlu[(r+8)*HSW + ca+4];
            Bah[0] = Hhu[r*HSW + cb];       Bal[0] = Hlu[r*HSW + cb];
            Bah[1] = Hhu[(r+8)*HSW + cb];   Bal[1] = Hlu[(r+8)*HSW + cb];
            Bah[2] = Hhu[r*HSW + cb+4];     Bal[2] = Hlu[r*HSW + cb+4];
            Bah[3] = Hhu[(r+8)*HSW + cb+4]; Bal[3] = Hlu[(r+8)*HSW + cb+4];
            #pragma unroll
            for (int nt = 0; nt < 2; nt++) {
                int ia = kp*64 + (nt*8 + gr)*4 + q;
                int ib = (kp+4)*64 + (nt*8 + gr)*4 + q;
                uint2 wha = w2h_r[kp][nt], whb = w2hb_r[kp][nt];
                uint2 wla = W2Lu[ia],      wlb = W2Lu[ib];
                mma16(da[nt], Aah[0], Aah[1], Aah[2], Aah[3], wha.x, wha.y);
                mma16(db[nt], Bah[0], Bah[1], Bah[2], Bah[3], whb.x, whb.y);
                mma16(da[nt], Aal[0], Aal[1], Aal[2], Aal[3], wha.x, wha.y);
                mma16(db[nt], Bal[0], Bal[1], Bal[2], Bal[3], whb.x, whb.y);
                mma16(da[nt], Aah[0], Aah[1], Aah[2], Aah[3], wla.x, wla.y);
                mma16(db[nt], Bah[0], Bah[1], Bah[2], Bah[3], wlb.x, wlb.y);
            }
        }

        // ---- output: reconstruct center from packed planes, add delta, re-split ----
        {
            int px0  = R2 + gr;
            int pix0 = y*Wn + x0 + px0;
            #pragma unroll
            for (int nt = 0; nt < 2; nt++) {
                int c0  = nt*8 + 2*q;
                int pcb = c0 >> 1;
                int rowoff = (pcb*3 + 1)*RSW + 1;       // center row of this pair-plane
                #pragma unroll
                for (int h = 0; h < 2; h++) {
                    int px  = px0  + 8*h;
                    int pix = pix0 + 8*h;
                    uint32_t cph = ru[rowoff + px];
                    uint32_t cpl = ru[RPLO + rowoff + px];
                    float ctr0 = lo_f(cph) + lo_f(cpl);
                    float ctr1 = hi_f(cph) + hi_f(cpl);
                    float d0 = da[nt][2*h]   + db[nt][2*h];
                    float d1 = da[nt][2*h+1] + db[nt][2*h+1];
                    float out0 = (c0 == 0) ? ctr0 : (ctr0 + d0);
                    float out1 = ctr1 + d1;
                    uint32_t ph = packbf(out1, out0);
                    dstPh[pcb*HWn + pix] = ph;
                    dstPl[pcb*HWn + pix] = packbf(out1 - hi_f(ph), out0 - lo_f(ph));
                    if (writeF32) {
                        dstF[c0*HWn + pix]     = out0;
                        dstF[(c0+1)*HWn + pix] = out1;
                    }
                }
            }
        }

        CP_WAIT0();
        __syncthreads();
        pb ^= 1;
    }
}

extern "C" void kernel_launch(void* const* d_in, const int* in_sizes, int n_in,
                              void* d_out, int out_size)
{
    const float* state = (const float*)d_in[0];
    const float* W1    = (const float*)d_in[1];
    const float* b1    = (const float*)d_in[2];
    const float* W2    = (const float*)d_in[3];
    const float* b2    = (const float*)d_in[4];
    float* out = (float*)d_out;

    cudaFuncSetAttribute(slime_step_mma,
                         cudaFuncAttributeMaxDynamicSharedMemorySize,
                         SMEM_WORDS * (int)sizeof(float));

    float* bufF;
    uint32_t *PhA, *PlA, *PhB, *PlB;
    cudaGetSymbolAddress((void**)&bufF, g_bufF);
    cudaGetSymbolAddress((void**)&PhA, g_PhA);
    cudaGetSymbolAddress((void**)&PlA, g_PlA);
    cudaGetSymbolAddress((void**)&PhB, g_PhB);
    cudaGetSymbolAddress((void**)&PlB, g_PlB);

    w_setup<<<1, 256>>>(W1, W2);
    pack_state<<<(8*HWn)/256, 256>>>(state, PhA, PlA);

    for (int s = 0; s < NSTEPS; s++) {
        const uint32_t* sPh = (s & 1) ? PhB : PhA;
        const uint32_t* sPl = (s & 1) ? PlB : PlA;
        uint32_t* dPh = (s & 1) ? PhA : PhB;
        uint32_t* dPl = (s & 1) ? PlA : PlB;
        int last = (s == NSTEPS-1);
        slime_step_mma<<<GRIDX, NTHREADS, SMEM_WORDS*sizeof(float)>>>(
            sPh, sPl, dPh, dPl, last ? out : bufF, last, b1, b2);
    }
}

// round 13
// speedup vs baseline: 1.8678x; 1.0901x over previous
#include <cuda_runtime.h>
#include <cstdint>

#define Cn 16
#define Hn 512
#define Wn 512
#define HWn (Hn*Wn)
#define NSTEPS 8
#define GRIDX 152
#define NTHREADS 256
#define NTILES 2048
#define RSW 136            // rows segment stride (words); px j at word 3+j
#define HSW 68             // H packed stride (words)
#define RPLO (24*RSW)      // lo-plane offset within rows buffer

// ---- smem word offsets ----
#define OFF_W1H 0                         // 5120 (uint2[5kc][128n][4q])
#define OFF_W1L 5120
#define OFF_W2H 10240                     // 1024 (uint2[8kc][16n][4q])
#define OFF_W2L 11264
#define OFF_B1  12288
#define OFF_B2  12416
#define OFF_R   12432                     // 2 x 48 segs x 136
#define RBUFSZ  (48*RSW)                  // 6528
#define OFF_HH  (OFF_R + 2*RBUFSZ)        // 25488
#define OFF_HL  (OFF_HH + 128*HSW)        // 34192
#define SMEM_WORDS (OFF_HL + 128*HSW)     // 42896 -> 171584 B

__device__ float    g_bufF[Cn*HWn];       // dummy f32 dst for warm steps
__device__ uint32_t g_PhA[8*HWn];
__device__ uint32_t g_PlA[8*HWn];
__device__ uint32_t g_PhB[8*HWn];
__device__ uint32_t g_PlB[8*HWn];
__device__ uint2    g_w1h[2560];
__device__ uint2    g_w1l[2560];
__device__ uint2    g_w2h[512];
__device__ uint2    g_w2l[512];

__device__ __forceinline__ uint32_t packbf(float hi, float lo) {
    uint32_t d;
    asm("cvt.rn.bf16x2.f32 %0, %1, %2;" : "=r"(d) : "f"(hi), "f"(lo));
    return d;
}
__device__ __forceinline__ float hi_f(uint32_t p) { return __uint_as_float(p & 0xFFFF0000u); }
__device__ __forceinline__ float lo_f(uint32_t p) { return __uint_as_float(p << 16); }

__device__ __forceinline__ uint32_t smem_u32(const void* p) {
    uint32_t a;
    asm("{ .reg .u64 t; cvta.to.shared.u64 t, %1; cvt.u32.u64 %0, t; }" : "=r"(a) : "l"(p));
    return a;
}
__device__ __forceinline__ void cpa4(uint32_t d, const void* g) {
    asm volatile("cp.async.ca.shared.global [%0], [%1], 4;" :: "r"(d), "l"(g));
}
__device__ __forceinline__ void cpa16(uint32_t d, const void* g) {
    asm volatile("cp.async.cg.shared.global [%0], [%1], 16;" :: "r"(d), "l"(g));
}
#define CP_COMMIT() asm volatile("cp.async.commit_group;" ::: "memory")
#define CP_WAIT0()  asm volatile("cp.async.wait_group 0;" ::: "memory")

__device__ __forceinline__ void mma16(float* d,
    uint32_t a0, uint32_t a1, uint32_t a2, uint32_t a3,
    uint32_t b0, uint32_t b1)
{
    asm volatile(
        "mma.sync.aligned.m16n8k16.row.col.f32.bf16.bf16.f32 "
        "{%0,%1,%2,%3}, {%4,%5,%6,%7}, {%8,%9}, {%0,%1,%2,%3};"
        : "+f"(d[0]), "+f"(d[1]), "+f"(d[2]), "+f"(d[3])
        : "r"(a0), "r"(a1), "r"(a2), "r"(a3), "r"(b0), "r"(b1));
}

// ---- weight bf16-split + packed-pair relayout ----
__global__ void w_setup(const float* __restrict__ W1, const float* __restrict__ W2) {
    int t = threadIdx.x;
    for (int i = t; i < 2560; i += 256) {        // W1[k][n], k<80
        int kc = i >> 9, rem = i & 511;
        int n = rem >> 2, q = rem & 3;
        int k0 = kc*16 + 2*q;
        float v0 = W1[(k0  )*128 + n], v1 = W1[(k0+1)*128 + n];
        float v8 = W1[(k0+8)*128 + n], v9 = W1[(k0+9)*128 + n];
        uint32_t h0 = packbf(v1, v0), h1 = packbf(v9, v8);
        g_w1h[i] = make_uint2(h0, h1);
        g_w1l[i] = make_uint2(packbf(v1 - hi_f(h0), v0 - lo_f(h0)),
                              packbf(v9 - hi_f(h1), v8 - lo_f(h1)));
    }
    for (int i = t; i < 512; i += 256) {         // W2[k][n], k<128
        int kc = i >> 6, rem = i & 63;
        int n = rem >> 2, q = rem & 3;
        int k0 = kc*16 + 2*q;
        float v0 = W2[(k0  )*16 + n], v1 = W2[(k0+1)*16 + n];
        float v8 = W2[(k0+8)*16 + n], v9 = W2[(k0+9)*16 + n];
        uint32_t h0 = packbf(v1, v0), h1 = packbf(v9, v8);
        g_w2h[i] = make_uint2(h0, h1);
        g_w2l[i] = make_uint2(packbf(v1 - hi_f(h0), v0 - lo_f(h0)),
                              packbf(v9 - hi_f(h1), v8 - lo_f(h1)));
    }
}

// ---- one-time: build packed channel-pair planes from input f32 state ----
__global__ void pack_state(const float* __restrict__ s,
                           uint32_t* __restrict__ Ph, uint32_t* __restrict__ Pl) {
    int i = blockIdx.x*256 + threadIdx.x;
    int pc = i >> 18, pix = i & (HWn-1);
    float v0 = s[(2*pc  )*HWn + pix];
    float v1 = s[(2*pc+1)*HWn + pix];
    uint32_t ph = packbf(v1, v0);
    Ph[i] = ph;
    Pl[i] = packbf(v1 - hi_f(ph), v0 - lo_f(ph));
}

// stage one tile: 48 packed segs; interior as 16B cp.async, 2 scalar edge words
__device__ __forceinline__ void stage_tile(const uint32_t* __restrict__ Ph,
                                           const uint32_t* __restrict__ Pl,
                                           uint32_t sbase, int rb,
                                           int y, int x0, int w, int lane)
{
    const int ym = (y == 0)    ? 0 : (y - 1);
    const int yp = (y == Hn-1) ? 0 : (y + 1);
    #pragma unroll 1
    for (int s = w; s < 48; s += 8) {
        uint32_t dbase = sbase + (uint32_t)(rb + s*RSW) * 4u;
        int plane = (s >= 24);
        int t2 = s - plane*24;
        int pc = t2 / 3, ri = t2 - pc*3;
        int gy = (ri == 0) ? ym : ((ri == 1) ? y : yp);
        const uint32_t* gsrc = (plane ? Pl : Ph) + pc*HWn + gy*Wn;
        // interior 128 px: 32 lanes x 16B, both sides 16B-aligned
        cpa16(dbase + 4u*(4 + 4*lane), gsrc + x0 + 4*lane);
        // edges: lane0 -> left halo (word 3), lane1 -> right halo (word 132)
        if (lane < 2) {
            int j  = lane ? 129 : 0;
            int gx = x0 - 1 + j;
            gx = (gx < 0)   ? 0 : gx;   // clamp low edge
            gx = (gx >= Wn) ? 0 : gx;   // wrap high edge
            cpa4(dbase + 4u*(3 + j), gsrc + gx);
        }
    }
}

__global__ void __launch_bounds__(NTHREADS, 1)
slime_step_mma(const uint32_t* __restrict__ srcPh, const uint32_t* __restrict__ srcPl,
               uint32_t* __restrict__ dstPh, uint32_t* __restrict__ dstPl,
               float* __restrict__ dstF, int writeF32,
               const float* __restrict__ gb1, const float* __restrict__ gb2)
{
    extern __shared__ float sm[];
    const uint32_t sbase = smem_u32(sm);
    const int tid = threadIdx.x;
    const int w = tid >> 5, lane = tid & 31;
    const int gr = lane >> 2, q = lane & 3;

    // ---- prologue: packed weights + biases to SMEM ----
    {
        uint4* d; const uint4* s;
        d = (uint4*)(sm + OFF_W1H); s = (const uint4*)g_w1h;
        #pragma unroll
        for (int i = 0; i < 5; i++) d[i*NTHREADS + tid] = s[i*NTHREADS + tid];
        d = (uint4*)(sm + OFF_W1L); s = (const uint4*)g_w1l;
        #pragma unroll
        for (int i = 0; i < 5; i++) d[i*NTHREADS + tid] = s[i*NTHREADS + tid];
        ((uint4*)(sm + OFF_W2H))[tid] = ((const uint4*)g_w2h)[tid];
        ((uint4*)(sm + OFF_W2L))[tid] = ((const uint4*)g_w2l)[tid];
        if (tid < 128) sm[OFF_B1 + tid] = gb1[tid];
        if (tid < 16)  sm[OFF_B2 + tid] = gb2[tid];
    }

    // ---- tile-invariant A offsets: px p at word 4+p; dir kc -> (ri,dx) ----
    int foH[10];
    {
        const int riA[5] = {1, 0, 2, 1, 1};
        const int dxA[5] = {0, 0, 0, -1, 1};
        #pragma unroll
        for (int kc = 0; kc < 5; kc++)
            #pragma unroll
            for (int p = 0; p < 2; p++)
                foH[kc*2+p] = ((q + 4*p)*3 + riA[kc])*RSW + 4 + dxA[kc];
    }

    const int R0 = (w >> 2) * 64, C0 = (w & 3) * 32;   // GEMM1 (2,4)
    const int R2 = w * 16;                              // GEMM2 16x16

    const uint2* W1Hu = (const uint2*)(sm + OFF_W1H);
    const uint2* W1Lu = (const uint2*)(sm + OFF_W1L);
    const uint2* W2Hu = (const uint2*)(sm + OFF_W2H);
    const uint2* W2Lu = (const uint2*)(sm + OFF_W2L);
    const float* b1s = sm + OFF_B1;
    const float* b2s = sm + OFF_B2;
    uint32_t* Hhu = (uint32_t*)(sm + OFF_HH);
    uint32_t* Hlu = (uint32_t*)(sm + OFF_HL);

    const int t0 = blockIdx.x;
    stage_tile(srcPh, srcPl, sbase, OFF_R, t0 >> 2, (t0 & 3) << 7, w, lane);
    CP_COMMIT();
    CP_WAIT0();
    __syncthreads();

    // ---- hoist tile-invariant W2-hi fragments into registers ----
    uint2 w2h_r[4][2], w2hb_r[4][2];
    #pragma unroll
    for (int kp = 0; kp < 4; kp++) {
        w2h_r[kp][0]  = W2Hu[kp*64 + (0*8 + gr)*4 + q];
        w2h_r[kp][1]  = W2Hu[kp*64 + (1*8 + gr)*4 + q];
        w2hb_r[kp][0] = W2Hu[(kp+4)*64 + (0*8 + gr)*4 + q];
        w2hb_r[kp][1] = W2Hu[(kp+4)*64 + (1*8 + gr)*4 + q];
    }

    int pb = 0;
    #pragma unroll 1
    for (int t = t0; t < NTILES; t += GRIDX) {
        const int y = t >> 2, x0 = (t & 3) << 7;
        const int rb  = OFF_R + (pb ? RBUFSZ : 0);
        const int rbn = OFF_R + (pb ? 0 : RBUFSZ);
        const uint32_t* ru = (const uint32_t*)(sm + rb);

        const int tn = t + GRIDX;
        if (tn < NTILES)
            stage_tile(srcPh, srcPl, sbase, rbn, tn >> 2, (tn & 3) << 7, w, lane);
        CP_COMMIT();

        // ============ GEMM1: D1 = X @ W1 (+b1), bf16 3-product ============
        float acc[4][4][4];
        #pragma unroll
        for (int nt = 0; nt < 4; nt++) {
            float bz0 = b1s[C0 + nt*8 + 2*q];
            float bz1 = b1s[C0 + nt*8 + 2*q + 1];
            #pragma unroll
            for (int mt = 0; mt < 4; mt++) {
                acc[mt][nt][0] = bz0; acc[mt][nt][1] = bz1;
                acc[mt][nt][2] = bz0; acc[mt][nt][3] = bz1;
            }
        }
        #pragma unroll
        for (int kc = 0; kc < 5; kc++) {
            const int o0 = foH[kc*2+0], o1 = foH[kc*2+1];
            uint32_t ah[4][4], al[4][4];
            #pragma unroll
            for (int mt = 0; mt < 4; mt++) {
                int r = R0 + mt*16 + gr;
                ah[mt][0] = ru[o0 + r];        al[mt][0] = ru[o0 + RPLO + r];
                ah[mt][1] = ru[o0 + r + 8];    al[mt][1] = ru[o0 + RPLO + r + 8];
                ah[mt][2] = ru[o1 + r];        al[mt][2] = ru[o1 + RPLO + r];
                ah[mt][3] = ru[o1 + r + 8];    al[mt][3] = ru[o1 + RPLO + r + 8];
            }
            uint2 bh[4], bl[4];
            #pragma unroll
            for (int nt = 0; nt < 4; nt++) {
                int idx = kc*512 + (C0 + nt*8 + gr)*4 + q;
                bh[nt] = W1Hu[idx];
                bl[nt] = W1Lu[idx];
            }
            #pragma unroll
            for (int nt = 0; nt < 4; nt++)
                #pragma unroll
                for (int mt = 0; mt < 4; mt++)
                    mma16(acc[mt][nt], ah[mt][0], ah[mt][1], ah[mt][2], ah[mt][3], bh[nt].x, bh[nt].y);
            #pragma unroll
            for (int nt = 0; nt < 4; nt++)
                #pragma unroll
                for (int mt = 0; mt < 4; mt++)
                    mma16(acc[mt][nt], al[mt][0], al[mt][1], al[mt][2], al[mt][3], bh[nt].x, bh[nt].y);
            #pragma unroll
            for (int nt = 0; nt < 4; nt++)
                #pragma unroll
                for (int mt = 0; mt < 4; mt++)
                    mma16(acc[mt][nt], ah[mt][0], ah[mt][1], ah[mt][2], ah[mt][3], bl[nt].x, bl[nt].y);
        }
        // ---- epilogue: H = relu(D1), packed bf16 hi/lo ----
        #pragma unroll
        for (int mt = 0; mt < 4; mt++) {
            int r = R0 + mt*16 + gr;
            #pragma unroll
            for (int nt = 0; nt < 4; nt++) {
                int pcc = (C0 >> 1) + nt*4 + q;
                float h0 = fmaxf(acc[mt][nt][0], 0.0f);
                float h1 = fmaxf(acc[mt][nt][1], 0.0f);
                float h2 = fmaxf(acc[mt][nt][2], 0.0f);
                float h3 = fmaxf(acc[mt][nt][3], 0.0f);
                uint32_t p0 = packbf(h1, h0);
                uint32_t p1 = packbf(h3, h2);
                Hhu[r*HSW + pcc]     = p0;
                Hhu[(r+8)*HSW + pcc] = p1;
                Hlu[r*HSW + pcc]     = packbf(h1 - hi_f(p0), h0 - lo_f(p0));
                Hlu[(r+8)*HSW + pcc] = packbf(h3 - hi_f(p1), h2 - lo_f(p1));
            }
        }
        __syncthreads();

        // ============ GEMM2: D2 = H @ W2 (+b2), bf16 3-product, K-split ============
        float da[2][4], db[2][4];
        #pragma unroll
        for (int nt = 0; nt < 2; nt++) {
            float bz0 = b2s[nt*8 + 2*q], bz1 = b2s[nt*8 + 2*q + 1];
            da[nt][0] = bz0; da[nt][1] = bz1; da[nt][2] = bz0; da[nt][3] = bz1;
            db[nt][0] = 0.f; db[nt][1] = 0.f; db[nt][2] = 0.f; db[nt][3] = 0.f;
        }
        #pragma unroll
        for (int kp = 0; kp < 4; kp++) {
            int r = R2 + gr;
            int ca = kp*8 + q, cb = (kp+4)*8 + q;
            uint32_t Aah[4], Aal[4], Bah[4], Bal[4];
            Aah[0] = Hhu[r*HSW + ca];       Aal[0] = Hlu[r*HSW + ca];
            Aah[1] = Hhu[(r+8)*HSW + ca];   Aal[1] = Hlu[(r+8)*HSW + ca];
            Aah[2] = Hhu[r*HSW + ca+4];     Aal[2] = Hlu[r*HSW + ca+4];
            Aah[3] = Hhu[(r+8)*HSW + ca+4]; Aal[3] = Hlu[(r+8)*HSW + ca+4];
            Bah[0] = Hhu[r*HSW + cb];       Bal[0] = Hlu[r*HSW + cb];
            Bah[1] = Hhu[(r+8)*HSW + cb];   Bal[1] = Hlu[(r+8)*HSW + cb];
            Bah[2] = Hhu[r*HSW + cb+4];     Bal[2] = Hlu[r*HSW + cb+4];
            Bah[3] = Hhu[(r+8)*HSW + cb+4]; Bal[3] = Hlu[(r+8)*HSW + cb+4];
            #pragma unroll
            for (int nt = 0; nt < 2; nt++) {
                int ia = kp*64 + (nt*8 + gr)*4 + q;
                int ib = (kp+4)*64 + (nt*8 + gr)*4 + q;
                uint2 wha = w2h_r[kp][nt], whb = w2hb_r[kp][nt];
                uint2 wla = W2Lu[ia],      wlb = W2Lu[ib];
                mma16(da[nt], Aah[0], Aah[1], Aah[2], Aah[3], wha.x, wha.y);
                mma16(db[nt], Bah[0], Bah[1], Bah[2], Bah[3], whb.x, whb.y);
                mma16(da[nt], Aal[0], Aal[1], Aal[2], Aal[3], wha.x, wha.y);
                mma16(db[nt], Bal[0], Bal[1], Bal[2], Bal[3], whb.x, whb.y);
                mma16(da[nt], Aah[0], Aah[1], Aah[2], Aah[3], wla.x, wla.y);
                mma16(db[nt], Bah[0], Bah[1], Bah[2], Bah[3], wlb.x, wlb.y);
            }
        }

        // ---- output: reconstruct center from packed planes, add delta, re-split ----
        {
            int px0  = R2 + gr;
            int pix0 = y*Wn + x0 + px0;
            #pragma unroll
            for (int nt = 0; nt < 2; nt++) {
                int c0  = nt*8 + 2*q;
                int pcb = c0 >> 1;
                int rowoff = (pcb*3 + 1)*RSW + 4;       // center row, px p at word 4+p
                #pragma unroll
                for (int h = 0; h < 2; h++) {
                    int px  = px0  + 8*h;
                    int pix = pix0 + 8*h;
                    uint32_t cph = ru[rowoff + px];
                    uint32_t cpl = ru[RPLO + rowoff + px];
                    float ctr0 = lo_f(cph) + lo_f(cpl);
                    float ctr1 = hi_f(cph) + hi_f(cpl);
                    float d0 = da[nt][2*h]   + db[nt][2*h];
                    float d1 = da[nt][2*h+1] + db[nt][2*h+1];
                    float out0 = (c0 == 0) ? ctr0 : (ctr0 + d0);
                    float out1 = ctr1 + d1;
                    uint32_t ph = packbf(out1, out0);
                    dstPh[pcb*HWn + pix] = ph;
                    dstPl[pcb*HWn + pix] = packbf(out1 - hi_f(ph), out0 - lo_f(ph));
                    if (writeF32) {
                        dstF[c0*HWn + pix]     = out0;
                        dstF[(c0+1)*HWn + pix] = out1;
                    }
                }
            }
        }

        CP_WAIT0();
        __syncthreads();
        pb ^= 1;
    }
}

extern "C" void kernel_launch(void* const* d_in, const int* in_sizes, int n_in,
                              void* d_out, int out_size)
{
    const float* state = (const float*)d_in[0];
    const float* W1    = (const float*)d_in[1];
    const float* b1    = (const float*)d_in[2];
    const float* W2    = (const float*)d_in[3];
    const float* b2    = (const float*)d_in[4];
    float* out = (float*)d_out;

    cudaFuncSetAttribute(slime_step_mma,
                         cudaFuncAttributeMaxDynamicSharedMemorySize,
                         SMEM_WORDS * (int)sizeof(float));

    float* bufF;
    uint32_t *PhA, *PlA, *PhB, *PlB;
    cudaGetSymbolAddress((void**)&bufF, g_bufF);
    cudaGetSymbolAddress((void**)&PhA, g_PhA);
    cudaGetSymbolAddress((void**)&PlA, g_PlA);
    cudaGetSymbolAddress((void**)&PhB, g_PhB);
    cudaGetSymbolAddress((void**)&PlB, g_PlB);

    w_setup<<<1, 256>>>(W1, W2);
    pack_state<<<(8*HWn)/256, 256>>>(state, PhA, PlA);

    for (int s = 0; s < NSTEPS; s++) {
        const uint32_t* sPh = (s & 1) ? PhB : PhA;
        const uint32_t* sPl = (s & 1) ? PlB : PlA;
        uint32_t* dPh = (s & 1) ? PhA : PhB;
        uint32_t* dPl = (s & 1) ? PlA : PlB;
        int last = (s == NSTEPS-1);
        slime_step_mma<<<GRIDX, NTHREADS, SMEM_WORDS*sizeof(float)>>>(
            sPh, sPl, dPh, dPl, last ? out : bufF, last, b1, b2);
    }
}

// round 14
// speedup vs baseline: 2.0023x; 1.0720x over previous
#include <cuda_runtime.h>
#include <cstdint>

#define Cn 16
#define Hn 512
#define Wn 512
#define HWn (Hn*Wn)
#define NSTEPS 8
#define GRIDX 152
#define NTHREADS 256
#define NTILES 2048
#define RSW 136            // rows segment stride (words); px j at word 3+j (interior at 4)
#define RPLO (24*RSW)      // lo-plane offset within rows buffer

// ---- smem word offsets ----
#define OFF_W1H 0                         // 5120 (uint2[5kc][128n][4q])
#define OFF_W1L 5120
#define OFF_W2H 10240                     // 1024 (uint2[8kc][16n][4q])
#define OFF_W2L 11264
#define OFF_B1  12288
#define OFF_B2  12416
#define OFF_R   12432                     // 2 x 48 segs x 136
#define RBUFSZ  (48*RSW)                  // 6528
#define SMEM_WORDS (OFF_R + 2*RBUFSZ)     // 25488 -> 101952 B

__device__ float    g_bufF[Cn*HWn];       // dummy f32 dst for warm steps
__device__ uint32_t g_PhA[8*HWn];
__device__ uint32_t g_PlA[8*HWn];
__device__ uint32_t g_PhB[8*HWn];
__device__ uint32_t g_PlB[8*HWn];
__device__ uint2    g_w1h[2560];
__device__ uint2    g_w1l[2560];
__device__ uint2    g_w2h[512];
__device__ uint2    g_w2l[512];

__device__ __forceinline__ uint32_t packbf(float hi, float lo) {
    uint32_t d;
    asm("cvt.rn.bf16x2.f32 %0, %1, %2;" : "=r"(d) : "f"(hi), "f"(lo));
    return d;
}
__device__ __forceinline__ float hi_f(uint32_t p) { return __uint_as_float(p & 0xFFFF0000u); }
__device__ __forceinline__ float lo_f(uint32_t p) { return __uint_as_float(p << 16); }

__device__ __forceinline__ uint32_t smem_u32(const void* p) {
    uint32_t a;
    asm("{ .reg .u64 t; cvta.to.shared.u64 t, %1; cvt.u32.u64 %0, t; }" : "=r"(a) : "l"(p));
    return a;
}
__device__ __forceinline__ void cpa4(uint32_t d, const void* g) {
    asm volatile("cp.async.ca.shared.global [%0], [%1], 4;" :: "r"(d), "l"(g));
}
__device__ __forceinline__ void cpa16(uint32_t d, const void* g) {
    asm volatile("cp.async.cg.shared.global [%0], [%1], 16;" :: "r"(d), "l"(g));
}
#define CP_COMMIT() asm volatile("cp.async.commit_group;" ::: "memory")
#define CP_WAIT0()  asm volatile("cp.async.wait_group 0;" ::: "memory")

__device__ __forceinline__ void mma16(float* d,
    uint32_t a0, uint32_t a1, uint32_t a2, uint32_t a3,
    uint32_t b0, uint32_t b1)
{
    asm volatile(
        "mma.sync.aligned.m16n8k16.row.col.f32.bf16.bf16.f32 "
        "{%0,%1,%2,%3}, {%4,%5,%6,%7}, {%8,%9}, {%0,%1,%2,%3};"
        : "+f"(d[0]), "+f"(d[1]), "+f"(d[2]), "+f"(d[3])
        : "r"(a0), "r"(a1), "r"(a2), "r"(a3), "r"(b0), "r"(b1));
}

// ---- weight bf16-split + packed-pair relayout ----
__global__ void w_setup(const float* __restrict__ W1, const float* __restrict__ W2) {
    int t = threadIdx.x;
    for (int i = t; i < 2560; i += 256) {        // W1[k][n], k<80
        int kc = i >> 9, rem = i & 511;
        int n = rem >> 2, q = rem & 3;
        int k0 = kc*16 + 2*q;
        float v0 = W1[(k0  )*128 + n], v1 = W1[(k0+1)*128 + n];
        float v8 = W1[(k0+8)*128 + n], v9 = W1[(k0+9)*128 + n];
        uint32_t h0 = packbf(v1, v0), h1 = packbf(v9, v8);
        g_w1h[i] = make_uint2(h0, h1);
        g_w1l[i] = make_uint2(packbf(v1 - hi_f(h0), v0 - lo_f(h0)),
                              packbf(v9 - hi_f(h1), v8 - lo_f(h1)));
    }
    for (int i = t; i < 512; i += 256) {         // W2[k][n], k<128
        int kc = i >> 6, rem = i & 63;
        int n = rem >> 2, q = rem & 3;
        int k0 = kc*16 + 2*q;
        float v0 = W2[(k0  )*16 + n], v1 = W2[(k0+1)*16 + n];
        float v8 = W2[(k0+8)*16 + n], v9 = W2[(k0+9)*16 + n];
        uint32_t h0 = packbf(v1, v0), h1 = packbf(v9, v8);
        g_w2h[i] = make_uint2(h0, h1);
        g_w2l[i] = make_uint2(packbf(v1 - hi_f(h0), v0 - lo_f(h0)),
                              packbf(v9 - hi_f(h1), v8 - lo_f(h1)));
    }
}

// ---- one-time: build packed channel-pair planes from input f32 state ----
__global__ void pack_state(const float* __restrict__ s,
                           uint32_t* __restrict__ Ph, uint32_t* __restrict__ Pl) {
    int i = blockIdx.x*256 + threadIdx.x;
    int pc = i >> 18, pix = i & (HWn-1);
    float v0 = s[(2*pc  )*HWn + pix];
    float v1 = s[(2*pc+1)*HWn + pix];
    uint32_t ph = packbf(v1, v0);
    Ph[i] = ph;
    Pl[i] = packbf(v1 - hi_f(ph), v0 - lo_f(ph));
}

// stage one tile: 48 packed segs; interior as 16B cp.async, 2 scalar edge words
__device__ __forceinline__ void stage_tile(const uint32_t* __restrict__ Ph,
                                           const uint32_t* __restrict__ Pl,
                                           uint32_t sbase, int rb,
                                           int y, int x0, int w, int lane)
{
    const int ym = (y == 0)    ? 0 : (y - 1);
    const int yp = (y == Hn-1) ? 0 : (y + 1);
    #pragma unroll 1
    for (int s = w; s < 48; s += 8) {
        uint32_t dbase = sbase + (uint32_t)(rb + s*RSW) * 4u;
        int plane = (s >= 24);
        int t2 = s - plane*24;
        int pc = t2 / 3, ri = t2 - pc*3;
        int gy = (ri == 0) ? ym : ((ri == 1) ? y : yp);
        const uint32_t* gsrc = (plane ? Pl : Ph) + pc*HWn + gy*Wn;
        cpa16(dbase + 4u*(4 + 4*lane), gsrc + x0 + 4*lane);
        if (lane < 2) {
            int j  = lane ? 129 : 0;
            int gx = x0 - 1 + j;
            gx = (gx < 0)   ? 0 : gx;   // clamp low edge
            gx = (gx >= Wn) ? 0 : gx;   // wrap high edge
            cpa4(dbase + 4u*(3 + j), gsrc + gx);
        }
    }
}

__global__ void __launch_bounds__(NTHREADS, 1)
slime_step_mma(const uint32_t* __restrict__ srcPh, const uint32_t* __restrict__ srcPl,
               uint32_t* __restrict__ dstPh, uint32_t* __restrict__ dstPl,
               float* __restrict__ dstF, int writeF32,
               const float* __restrict__ gb1, const float* __restrict__ gb2)
{
    extern __shared__ float sm[];
    const uint32_t sbase = smem_u32(sm);
    const int tid = threadIdx.x;
    const int w = tid >> 5, lane = tid & 31;
    const int gr = lane >> 2, q = lane & 3;

    // ---- prologue: packed weights + biases to SMEM ----
    {
        uint4* d; const uint4* s;
        d = (uint4*)(sm + OFF_W1H); s = (const uint4*)g_w1h;
        #pragma unroll
        for (int i = 0; i < 5; i++) d[i*NTHREADS + tid] = s[i*NTHREADS + tid];
        d = (uint4*)(sm + OFF_W1L); s = (const uint4*)g_w1l;
        #pragma unroll
        for (int i = 0; i < 5; i++) d[i*NTHREADS + tid] = s[i*NTHREADS + tid];
        ((uint4*)(sm + OFF_W2H))[tid] = ((const uint4*)g_w2h)[tid];
        ((uint4*)(sm + OFF_W2L))[tid] = ((const uint4*)g_w2l)[tid];
        if (tid < 128) sm[OFF_B1 + tid] = gb1[tid];
        if (tid < 16)  sm[OFF_B2 + tid] = gb2[tid];
    }

    // ---- tile-invariant A offsets: px p at word 4+p; dir kc -> (ri,dx) ----
    int foH[10];
    {
        const int riA[5] = {1, 0, 2, 1, 1};
        const int dxA[5] = {0, 0, 0, -1, 1};
        #pragma unroll
        for (int kc = 0; kc < 5; kc++)
            #pragma unroll
            for (int p = 0; p < 2; p++)
                foH[kc*2+p] = ((q + 4*p)*3 + riA[kc])*RSW + 4 + dxA[kc];
    }

    const int R2 = w * 16;                 // warp owns 16 px: rows R2..R2+15

    const uint2* W1Hu = (const uint2*)(sm + OFF_W1H);
    const uint2* W1Lu = (const uint2*)(sm + OFF_W1L);
    const uint2* W2Hu = (const uint2*)(sm + OFF_W2H);
    const uint2* W2Lu = (const uint2*)(sm + OFF_W2L);
    const float* b1s = sm + OFF_B1;
    const float* b2s = sm + OFF_B2;

    const int t0 = blockIdx.x;
    stage_tile(srcPh, srcPl, sbase, OFF_R, t0 >> 2, (t0 & 3) << 7, w, lane);
    CP_COMMIT();
    CP_WAIT0();
    __syncthreads();

    int pb = 0;
    #pragma unroll 1
    for (int t = t0; t < NTILES; t += GRIDX) {
        const int y = t >> 2, x0 = (t & 3) << 7;
        const int rb  = OFF_R + (pb ? RBUFSZ : 0);
        const int rbn = OFF_R + (pb ? 0 : RBUFSZ);
        const uint32_t* ru = (const uint32_t*)(sm + rb);

        const int tn = t + GRIDX;
        if (tn < NTILES)
            stage_tile(srcPh, srcPl, sbase, rbn, tn >> 2, (tn & 3) << 7, w, lane);
        CP_COMMIT();

        // ===== GEMM1: warp tile 16px x 128hid, bf16 3-product, A reused across nt =====
        float acc[16][4];
        #pragma unroll
        for (int nt = 0; nt < 16; nt++) {
            float bz0 = b1s[nt*8 + 2*q];
            float bz1 = b1s[nt*8 + 2*q + 1];
            acc[nt][0] = bz0; acc[nt][1] = bz1;
            acc[nt][2] = bz0; acc[nt][3] = bz1;
        }
        #pragma unroll
        for (int kc = 0; kc < 5; kc++) {
            const int o0 = foH[kc*2+0], o1 = foH[kc*2+1];
            const int r = R2 + gr;
            uint32_t a0h = ru[o0 + r],     a0l = ru[o0 + RPLO + r];
            uint32_t a1h = ru[o0 + r + 8], a1l = ru[o0 + RPLO + r + 8];
            uint32_t a2h = ru[o1 + r],     a2l = ru[o1 + RPLO + r];
            uint32_t a3h = ru[o1 + r + 8], a3l = ru[o1 + RPLO + r + 8];
            #pragma unroll
            for (int half = 0; half < 2; half++) {
                uint2 bh[8], bl[8];
                #pragma unroll
                for (int j = 0; j < 8; j++) {
                    int idx = kc*512 + ((half*8 + j)*8 + gr)*4 + q;
                    bh[j] = W1Hu[idx];
                    bl[j] = W1Lu[idx];
                }
                #pragma unroll
                for (int j = 0; j < 8; j++)
                    mma16(acc[half*8+j], a0h, a1h, a2h, a3h, bh[j].x, bh[j].y);
                #pragma unroll
                for (int j = 0; j < 8; j++)
                    mma16(acc[half*8+j], a0l, a1l, a2l, a3l, bh[j].x, bh[j].y);
                #pragma unroll
                for (int j = 0; j < 8; j++)
                    mma16(acc[half*8+j], a0h, a1h, a2h, a3h, bl[j].x, bl[j].y);
            }
        }

        // ===== pack H in registers: relu + bf16 hi/lo split (no SMEM, no barrier) =====
        uint32_t Hh[8][4], Hl[8][4];
        #pragma unroll
        for (int kp = 0; kp < 8; kp++) {
            #pragma unroll
            for (int j = 0; j < 2; j++) {              // j=0: k-low 8 (nt=2kp), j=1: k-high (nt=2kp+1)
                float h0 = fmaxf(acc[2*kp+j][0], 0.0f);
                float h1 = fmaxf(acc[2*kp+j][1], 0.0f);
                float h2 = fmaxf(acc[2*kp+j][2], 0.0f);
                float h3 = fmaxf(acc[2*kp+j][3], 0.0f);
                uint32_t p0 = packbf(h1, h0);          // row r
                uint32_t p1 = packbf(h3, h2);          // row r+8
                Hh[kp][2*j]   = p0;
                Hh[kp][2*j+1] = p1;
                Hl[kp][2*j]   = packbf(h1 - hi_f(p0), h0 - lo_f(p0));
                Hl[kp][2*j+1] = packbf(h3 - hi_f(p1), h2 - lo_f(p1));
            }
        }

        // ===== GEMM2: D2 = H @ W2 (+b2), bf16 3-product, dual K-chains =====
        float da[2][4], db[2][4];
        #pragma unroll
        for (int nt = 0; nt < 2; nt++) {
            float bz0 = b2s[nt*8 + 2*q], bz1 = b2s[nt*8 + 2*q + 1];
            da[nt][0] = bz0; da[nt][1] = bz1; da[nt][2] = bz0; da[nt][3] = bz1;
            db[nt][0] = 0.f; db[nt][1] = 0.f; db[nt][2] = 0.f; db[nt][3] = 0.f;
        }
        #pragma unroll
        for (int kp = 0; kp < 4; kp++) {
            uint2 wha[2], wla[2], whb[2], wlb[2];
            #pragma unroll
            for (int nt = 0; nt < 2; nt++) {
                int ia = kp*64 + (nt*8 + gr)*4 + q;
                int ib = (kp+4)*64 + (nt*8 + gr)*4 + q;
                wha[nt] = W2Hu[ia]; wla[nt] = W2Lu[ia];
                whb[nt] = W2Hu[ib]; wlb[nt] = W2Lu[ib];
            }
            // term hh (spacing-4 interleave of 4 accumulator chains)
            mma16(da[0], Hh[kp][0], Hh[kp][1], Hh[kp][2], Hh[kp][3], wha[0].x, wha[0].y);
            mma16(db[0], Hh[kp+4][0], Hh[kp+4][1], Hh[kp+4][2], Hh[kp+4][3], whb[0].x, whb[0].y);
            mma16(da[1], Hh[kp][0], Hh[kp][1], Hh[kp][2], Hh[kp][3], wha[1].x, wha[1].y);
            mma16(db[1], Hh[kp+4][0], Hh[kp+4][1], Hh[kp+4][2], Hh[kp+4][3], whb[1].x, whb[1].y);
            // term lh (A-lo)
            mma16(da[0], Hl[kp][0], Hl[kp][1], Hl[kp][2], Hl[kp][3], wha[0].x, wha[0].y);
            mma16(db[0], Hl[kp+4][0], Hl[kp+4][1], Hl[kp+4][2], Hl[kp+4][3], whb[0].x, whb[0].y);
            mma16(da[1], Hl[kp][0], Hl[kp][1], Hl[kp][2], Hl[kp][3], wha[1].x, wha[1].y);
            mma16(db[1], Hl[kp+4][0], Hl[kp+4][1], Hl[kp+4][2], Hl[kp+4][3], whb[1].x, whb[1].y);
            // term hl (B-lo)
            mma16(da[0], Hh[kp][0], Hh[kp][1], Hh[kp][2], Hh[kp][3], wla[0].x, wla[0].y);
            mma16(db[0], Hh[kp+4][0], Hh[kp+4][1], Hh[kp+4][2], Hh[kp+4][3], wlb[0].x, wlb[0].y);
            mma16(da[1], Hh[kp][0], Hh[kp][1], Hh[kp][2], Hh[kp][3], wla[1].x, wla[1].y);
            mma16(db[1], Hh[kp+4][0], Hh[kp+4][1], Hh[kp+4][2], Hh[kp+4][3], wlb[1].x, wlb[1].y);
        }

        // ---- output: reconstruct center from packed planes, add delta, re-split ----
        {
            int px0  = R2 + gr;
            int pix0 = y*Wn + x0 + px0;
            #pragma unroll
            for (int nt = 0; nt < 2; nt++) {
                int c0  = nt*8 + 2*q;
                int pcb = c0 >> 1;
                int rowoff = (pcb*3 + 1)*RSW + 4;       // center row, px p at word 4+p
                #pragma unroll
                for (int h = 0; h < 2; h++) {
                    int px  = px0  + 8*h;
                    int pix = pix0 + 8*h;
                    uint32_t cph = ru[rowoff + px];
                    uint32_t cpl = ru[RPLO + rowoff + px];
                    float ctr0 = lo_f(cph) + lo_f(cpl);
                    float ctr1 = hi_f(cph) + hi_f(cpl);
                    float d0 = da[nt][2*h]   + db[nt][2*h];
                    float d1 = da[nt][2*h+1] + db[nt][2*h+1];
                    float out0 = (c0 == 0) ? ctr0 : (ctr0 + d0);
                    float out1 = ctr1 + d1;
                    uint32_t ph = packbf(out1, out0);
                    dstPh[pcb*HWn + pix] = ph;
                    dstPl[pcb*HWn + pix] = packbf(out1 - hi_f(ph), out0 - lo_f(ph));
                    if (writeF32) {
                        dstF[c0*HWn + pix]     = out0;
                        dstF[(c0+1)*HWn + pix] = out1;
                    }
                }
            }
        }

        CP_WAIT0();
        __syncthreads();
        pb ^= 1;
    }
}

extern "C" void kernel_launch(void* const* d_in, const int* in_sizes, int n_in,
                              void* d_out, int out_size)
{
    const float* state = (const float*)d_in[0];
    const float* W1    = (const float*)d_in[1];
    const float* b1    = (const float*)d_in[2];
    const float* W2    = (const float*)d_in[3];
    const float* b2    = (const float*)d_in[4];
    float* out = (float*)d_out;

    cudaFuncSetAttribute(slime_step_mma,
                         cudaFuncAttributeMaxDynamicSharedMemorySize,
                         SMEM_WORDS * (int)sizeof(float));

    float* bufF;
    uint32_t *PhA, *PlA, *PhB, *PlB;
    cudaGetSymbolAddress((void**)&bufF, g_bufF);
    cudaGetSymbolAddress((void**)&PhA, g_PhA);
    cudaGetSymbolAddress((void**)&PlA, g_PlA);
    cudaGetSymbolAddress((void**)&PhB, g_PhB);
    cudaGetSymbolAddress((void**)&PlB, g_PlB);

    w_setup<<<1, 256>>>(W1, W2);
    pack_state<<<(8*HWn)/256, 256>>>(state, PhA, PlA);

    for (int s = 0; s < NSTEPS; s++) {
        const uint32_t* sPh = (s & 1) ? PhB : PhA;
        const uint32_t* sPl = (s & 1) ? PlB : PlA;
        uint32_t* dPh = (s & 1) ? PhA : PhB;
        uint32_t* dPl = (s & 1) ? PlA : PlB;
        int last = (s == NSTEPS-1);
        slime_step_mma<<<GRIDX, NTHREADS, SMEM_WORDS*sizeof(float)>>>(
            sPh, sPl, dPh, dPl, last ? out : bufF, last, b1, b2);
    }
}

// round 15
// speedup vs baseline: 2.1462x; 1.0719x over previous
#include <cuda_runtime.h>
#include <cstdint>

#define Cn 16
#define Hn 512
#define Wn 512
#define HWn (Hn*Wn)
#define NSTEPS 8
#define GRIDX 304          // 2 CTAs per SM
#define NTHREADS 256
#define NTILES 2048
#define RSW 136            // rows segment stride (words); interior px p at word 4+p
#define RPLO (24*RSW)      // lo-plane offset within rows buffer

// ---- smem word offsets ----
#define OFF_W1H 0                         // 5120 (uint2[5kc][128n][4q])
#define OFF_W1L 5120
#define OFF_W2H 10240                     // 1024 (uint2[8kc][16n][4q])
#define OFF_W2L 11264
#define OFF_B1  12288
#define OFF_B2  12416
#define OFF_R   12432                     // 2 x 48 segs x 136
#define RBUFSZ  (48*RSW)                  // 6528
#define SMEM_WORDS (OFF_R + 2*RBUFSZ)     // 25488 -> 101952 B (x2 CTA = 204KB <= 227KB)

__device__ float    g_bufF[Cn*HWn];       // dummy f32 dst for warm steps
__device__ uint32_t g_PhA[8*HWn];
__device__ uint32_t g_PlA[8*HWn];
__device__ uint32_t g_PhB[8*HWn];
__device__ uint32_t g_PlB[8*HWn];
__device__ uint2    g_w1h[2560];
__device__ uint2    g_w1l[2560];
__device__ uint2    g_w2h[512];
__device__ uint2    g_w2l[512];

__device__ __forceinline__ uint32_t packbf(float hi, float lo) {
    uint32_t d;
    asm("cvt.rn.bf16x2.f32 %0, %1, %2;" : "=r"(d) : "f"(hi), "f"(lo));
    return d;
}
__device__ __forceinline__ float hi_f(uint32_t p) { return __uint_as_float(p & 0xFFFF0000u); }
__device__ __forceinline__ float lo_f(uint32_t p) { return __uint_as_float(p << 16); }

__device__ __forceinline__ uint32_t smem_u32(const void* p) {
    uint32_t a;
    asm("{ .reg .u64 t; cvta.to.shared.u64 t, %1; cvt.u32.u64 %0, t; }" : "=r"(a) : "l"(p));
    return a;
}
__device__ __forceinline__ void cpa4(uint32_t d, const void* g) {
    asm volatile("cp.async.ca.shared.global [%0], [%1], 4;" :: "r"(d), "l"(g));
}
__device__ __forceinline__ void cpa16(uint32_t d, const void* g) {
    asm volatile("cp.async.cg.shared.global [%0], [%1], 16;" :: "r"(d), "l"(g));
}
#define CP_COMMIT() asm volatile("cp.async.commit_group;" ::: "memory")
#define CP_WAIT0()  asm volatile("cp.async.wait_group 0;" ::: "memory")

__device__ __forceinline__ void mma16(float* d,
    uint32_t a0, uint32_t a1, uint32_t a2, uint32_t a3,
    uint32_t b0, uint32_t b1)
{
    asm volatile(
        "mma.sync.aligned.m16n8k16.row.col.f32.bf16.bf16.f32 "
        "{%0,%1,%2,%3}, {%4,%5,%6,%7}, {%8,%9}, {%0,%1,%2,%3};"
        : "+f"(d[0]), "+f"(d[1]), "+f"(d[2]), "+f"(d[3])
        : "r"(a0), "r"(a1), "r"(a2), "r"(a3), "r"(b0), "r"(b1));
}

// ---- weight bf16-split + packed-pair relayout ----
__global__ void w_setup(const float* __restrict__ W1, const float* __restrict__ W2) {
    int t = threadIdx.x;
    for (int i = t; i < 2560; i += 256) {        // W1[k][n], k<80
        int kc = i >> 9, rem = i & 511;
        int n = rem >> 2, q = rem & 3;
        int k0 = kc*16 + 2*q;
        float v0 = W1[(k0  )*128 + n], v1 = W1[(k0+1)*128 + n];
        float v8 = W1[(k0+8)*128 + n], v9 = W1[(k0+9)*128 + n];
        uint32_t h0 = packbf(v1, v0), h1 = packbf(v9, v8);
        g_w1h[i] = make_uint2(h0, h1);
        g_w1l[i] = make_uint2(packbf(v1 - hi_f(h0), v0 - lo_f(h0)),
                              packbf(v9 - hi_f(h1), v8 - lo_f(h1)));
    }
    for (int i = t; i < 512; i += 256) {         // W2[k][n], k<128
        int kc = i >> 6, rem = i & 63;
        int n = rem >> 2, q = rem & 3;
        int k0 = kc*16 + 2*q;
        float v0 = W2[(k0  )*16 + n], v1 = W2[(k0+1)*16 + n];
        float v8 = W2[(k0+8)*16 + n], v9 = W2[(k0+9)*16 + n];
        uint32_t h0 = packbf(v1, v0), h1 = packbf(v9, v8);
        g_w2h[i] = make_uint2(h0, h1);
        g_w2l[i] = make_uint2(packbf(v1 - hi_f(h0), v0 - lo_f(h0)),
                              packbf(v9 - hi_f(h1), v8 - lo_f(h1)));
    }
}

// ---- one-time: build packed channel-pair planes from input f32 state ----
__global__ void pack_state(const float* __restrict__ s,
                           uint32_t* __restrict__ Ph, uint32_t* __restrict__ Pl) {
    int i = blockIdx.x*256 + threadIdx.x;
    int pc = i >> 18, pix = i & (HWn-1);
    float v0 = s[(2*pc  )*HWn + pix];
    float v1 = s[(2*pc+1)*HWn + pix];
    uint32_t ph = packbf(v1, v0);
    Ph[i] = ph;
    Pl[i] = packbf(v1 - hi_f(ph), v0 - lo_f(ph));
}

// stage one tile: 48 packed segs; interior as 16B cp.async, 2 scalar edge words
__device__ __forceinline__ void stage_tile(const uint32_t* __restrict__ Ph,
                                           const uint32_t* __restrict__ Pl,
                                           uint32_t sbase, int rb,
                                           int y, int x0, int w, int lane)
{
    const int ym = (y == 0)    ? 0 : (y - 1);
    const int yp = (y == Hn-1) ? 0 : (y + 1);
    #pragma unroll 1
    for (int s = w; s < 48; s += 8) {
        uint32_t dbase = sbase + (uint32_t)(rb + s*RSW) * 4u;
        int plane = (s >= 24);
        int t2 = s - plane*24;
        int pc = t2 / 3, ri = t2 - pc*3;
        int gy = (ri == 0) ? ym : ((ri == 1) ? y : yp);
        const uint32_t* gsrc = (plane ? Pl : Ph) + pc*HWn + gy*Wn;
        cpa16(dbase + 4u*(4 + 4*lane), gsrc + x0 + 4*lane);
        if (lane < 2) {
            int j  = lane ? 129 : 0;
            int gx = x0 - 1 + j;
            gx = (gx < 0)   ? 0 : gx;   // clamp low edge
            gx = (gx >= Wn) ? 0 : gx;   // wrap high edge
            cpa4(dbase + 4u*(3 + j), gsrc + gx);
        }
    }
}

__global__ void __launch_bounds__(NTHREADS, 2)
slime_step_mma(const uint32_t* __restrict__ srcPh, const uint32_t* __restrict__ srcPl,
               uint32_t* __restrict__ dstPh, uint32_t* __restrict__ dstPl,
               float* __restrict__ dstF, int writeF32,
               const float* __restrict__ gb1, const float* __restrict__ gb2)
{
    extern __shared__ float sm[];
    const uint32_t sbase = smem_u32(sm);
    const int tid = threadIdx.x;
    const int w = tid >> 5, lane = tid & 31;
    const int gr = lane >> 2, q = lane & 3;

    // ---- prologue: packed weights + biases to SMEM ----
    {
        uint4* d; const uint4* s;
        d = (uint4*)(sm + OFF_W1H); s = (const uint4*)g_w1h;
        #pragma unroll
        for (int i = 0; i < 5; i++) d[i*NTHREADS + tid] = s[i*NTHREADS + tid];
        d = (uint4*)(sm + OFF_W1L); s = (const uint4*)g_w1l;
        #pragma unroll
        for (int i = 0; i < 5; i++) d[i*NTHREADS + tid] = s[i*NTHREADS + tid];
        ((uint4*)(sm + OFF_W2H))[tid] = ((const uint4*)g_w2h)[tid];
        ((uint4*)(sm + OFF_W2L))[tid] = ((const uint4*)g_w2l)[tid];
        if (tid < 128) sm[OFF_B1 + tid] = gb1[tid];
        if (tid < 16)  sm[OFF_B2 + tid] = gb2[tid];
    }

    // ---- tile-invariant A offsets: px p at word 4+p; dir kc -> (ri,dx) ----
    int foH[10];
    {
        const int riA[5] = {1, 0, 2, 1, 1};
        const int dxA[5] = {0, 0, 0, -1, 1};
        #pragma unroll
        for (int kc = 0; kc < 5; kc++)
            #pragma unroll
            for (int p = 0; p < 2; p++)
                foH[kc*2+p] = ((q + 4*p)*3 + riA[kc])*RSW + 4 + dxA[kc];
    }

    const int R2 = w * 16;                 // warp owns 16 px

    const uint2* W1Hu = (const uint2*)(sm + OFF_W1H);
    const uint2* W1Lu = (const uint2*)(sm + OFF_W1L);
    const uint2* W2Hu = (const uint2*)(sm + OFF_W2H);
    const uint2* W2Lu = (const uint2*)(sm + OFF_W2L);
    const float* b1s = sm + OFF_B1;
    const float* b2s = sm + OFF_B2;

    const int t0 = blockIdx.x;
    if (t0 < NTILES)
        stage_tile(srcPh, srcPl, sbase, OFF_R, t0 >> 2, (t0 & 3) << 7, w, lane);
    CP_COMMIT();
    CP_WAIT0();
    __syncthreads();

    int pb = 0;
    #pragma unroll 1
    for (int t = t0; t < NTILES; t += GRIDX) {
        const int y = t >> 2, x0 = (t & 3) << 7;
        const int rb  = OFF_R + (pb ? RBUFSZ : 0);
        const int rbn = OFF_R + (pb ? 0 : RBUFSZ);
        const uint32_t* ru = (const uint32_t*)(sm + rb);

        const int tn = t + GRIDX;
        if (tn < NTILES)
            stage_tile(srcPh, srcPl, sbase, rbn, tn >> 2, (tn & 3) << 7, w, lane);
        CP_COMMIT();

        // GEMM2 output chains (da: even kp, db: odd kp)
        float da[2][4], db[2][4];
        #pragma unroll
        for (int nt = 0; nt < 2; nt++) {
            float bz0 = b2s[nt*8 + 2*q], bz1 = b2s[nt*8 + 2*q + 1];
            da[nt][0] = bz0; da[nt][1] = bz1; da[nt][2] = bz0; da[nt][3] = bz1;
            db[nt][0] = 0.f; db[nt][1] = 0.f; db[nt][2] = 0.f; db[nt][3] = 0.f;
        }

        // ===== two hidden-halves: GEMM1 half -> fused pack + GEMM2 half =====
        #pragma unroll
        for (int hh2 = 0; hh2 < 2; hh2++) {
            float acc[8][4];
            #pragma unroll
            for (int j = 0; j < 8; j++) {
                int nt = hh2*8 + j;
                float bz0 = b1s[nt*8 + 2*q];
                float bz1 = b1s[nt*8 + 2*q + 1];
                acc[j][0] = bz0; acc[j][1] = bz1;
                acc[j][2] = bz0; acc[j][3] = bz1;
            }
            #pragma unroll
            for (int kc = 0; kc < 5; kc++) {
                const int o0 = foH[kc*2+0], o1 = foH[kc*2+1];
                const int r = R2 + gr;
                uint32_t a0h = ru[o0 + r],     a0l = ru[o0 + RPLO + r];
                uint32_t a1h = ru[o0 + r + 8], a1l = ru[o0 + RPLO + r + 8];
                uint32_t a2h = ru[o1 + r],     a2l = ru[o1 + RPLO + r];
                uint32_t a3h = ru[o1 + r + 8], a3l = ru[o1 + RPLO + r + 8];
                uint2 bh[8], bl[8];
                #pragma unroll
                for (int j = 0; j < 8; j++) {
                    int idx = kc*512 + ((hh2*8 + j)*8 + gr)*4 + q;
                    bh[j] = W1Hu[idx];
                    bl[j] = W1Lu[idx];
                }
                #pragma unroll
                for (int j = 0; j < 8; j++)
                    mma16(acc[j], a0h, a1h, a2h, a3h, bh[j].x, bh[j].y);
                #pragma unroll
                for (int j = 0; j < 8; j++)
                    mma16(acc[j], a0l, a1l, a2l, a3l, bh[j].x, bh[j].y);
                #pragma unroll
                for (int j = 0; j < 8; j++)
                    mma16(acc[j], a0h, a1h, a2h, a3h, bl[j].x, bl[j].y);
            }

            // fused epilogue + GEMM2 for this half's 4 k-chunks
            #pragma unroll
            for (int kp4 = 0; kp4 < 4; kp4++) {
                int kp = hh2*4 + kp4;
                uint32_t hhv[4], hlv[4];
                #pragma unroll
                for (int j = 0; j < 2; j++) {
                    float h0 = fmaxf(acc[2*kp4+j][0], 0.0f);
                    float h1 = fmaxf(acc[2*kp4+j][1], 0.0f);
                    float h2 = fmaxf(acc[2*kp4+j][2], 0.0f);
                    float h3 = fmaxf(acc[2*kp4+j][3], 0.0f);
                    uint32_t p0 = packbf(h1, h0);
                    uint32_t p1 = packbf(h3, h2);
                    hhv[2*j]   = p0;
                    hhv[2*j+1] = p1;
                    hlv[2*j]   = packbf(h1 - hi_f(p0), h0 - lo_f(p0));
                    hlv[2*j+1] = packbf(h3 - hi_f(p1), h2 - lo_f(p1));
                }
                uint2 wh[2], wl[2];
                #pragma unroll
                for (int nt = 0; nt < 2; nt++) {
                    int ia = kp*64 + (nt*8 + gr)*4 + q;
                    wh[nt] = W2Hu[ia];
                    wl[nt] = W2Lu[ia];
                }
                float (*dd)[4] = (kp4 & 1) ? db : da;
                mma16(dd[0], hhv[0], hhv[1], hhv[2], hhv[3], wh[0].x, wh[0].y);
                mma16(dd[1], hhv[0], hhv[1], hhv[2], hhv[3], wh[1].x, wh[1].y);
                mma16(dd[0], hlv[0], hlv[1], hlv[2], hlv[3], wh[0].x, wh[0].y);
                mma16(dd[1], hlv[0], hlv[1], hlv[2], hlv[3], wh[1].x, wh[1].y);
                mma16(dd[0], hhv[0], hhv[1], hhv[2], hhv[3], wl[0].x, wl[0].y);
                mma16(dd[1], hhv[0], hhv[1], hhv[2], hhv[3], wl[1].x, wl[1].y);
            }
        }

        // ---- output: reconstruct center from packed planes, add delta, re-split ----
        {
            int px0  = R2 + gr;
            int pix0 = y*Wn + x0 + px0;
            #pragma unroll
            for (int nt = 0; nt < 2; nt++) {
                int c0  = nt*8 + 2*q;
                int pcb = c0 >> 1;
                int rowoff = (pcb*3 + 1)*RSW + 4;       // center row, px p at word 4+p
                #pragma unroll
                for (int h = 0; h < 2; h++) {
                    int px  = px0  + 8*h;
                    int pix = pix0 + 8*h;
                    uint32_t cph = ru[rowoff + px];
                    uint32_t cpl = ru[RPLO + rowoff + px];
                    float ctr0 = lo_f(cph) + lo_f(cpl);
                    float ctr1 = hi_f(cph) + hi_f(cpl);
                    float d0 = da[nt][2*h]   + db[nt][2*h];
                    float d1 = da[nt][2*h+1] + db[nt][2*h+1];
                    float out0 = (c0 == 0) ? ctr0 : (ctr0 + d0);
                    float out1 = ctr1 + d1;
                    uint32_t ph = packbf(out1, out0);
                    dstPh[pcb*HWn + pix] = ph;
                    dstPl[pcb*HWn + pix] = packbf(out1 - hi_f(ph), out0 - lo_f(ph));
                    if (writeF32) {
                        dstF[c0*HWn + pix]     = out0;
                        dstF[(c0+1)*HWn + pix] = out1;
                    }
                }
            }
        }

        CP_WAIT0();
        __syncthreads();
        pb ^= 1;
    }
}

extern "C" void kernel_launch(void* const* d_in, const int* in_sizes, int n_in,
                              void* d_out, int out_size)
{
    const float* state = (const float*)d_in[0];
    const float* W1    = (const float*)d_in[1];
    const float* b1    = (const float*)d_in[2];
    const float* W2    = (const float*)d_in[3];
    const float* b2    = (const float*)d_in[4];
    float* out = (float*)d_out;

    cudaFuncSetAttribute(slime_step_mma,
                         cudaFuncAttributeMaxDynamicSharedMemorySize,
                         SMEM_WORDS * (int)sizeof(float));

    float* bufF;
    uint32_t *PhA, *PlA, *PhB, *PlB;
    cudaGetSymbolAddress((void**)&bufF, g_bufF);
    cudaGetSymbolAddress((void**)&PhA, g_PhA);
    cudaGetSymbolAddress((void**)&PlA, g_PlA);
    cudaGetSymbolAddress((void**)&PhB, g_PhB);
    cudaGetSymbolAddress((void**)&PlB, g_PlB);

    w_setup<<<1, 256>>>(W1, W2);
    pack_state<<<(8*HWn)/256, 256>>>(state, PhA, PlA);

    for (int s = 0; s < NSTEPS; s++) {
        const uint32_t* sPh = (s & 1) ? PhB : PhA;
        const uint32_t* sPl = (s & 1) ? PlB : PlA;
        uint32_t* dPh = (s & 1) ? PhA : PhB;
        uint32_t* dPl = (s & 1) ? PlA : PlB;
        int last = (s == NSTEPS-1);
        slime_step_mma<<<GRIDX, NTHREADS, SMEM_WORDS*sizeof(float)>>>(
            sPh, sPl, dPh, dPl, last ? out : bufF, last, b1, b2);
    }
}